// round 3
// baseline (speedup 1.0000x reference)
#include <cuda_runtime.h>
#include <math.h>

#define BB 32
#define NN 512
#define NF 128
#define FH 64
#define NH 8
#define NC 16
#define ALPHA 0.2f
#define NEGINF -9e15f

// ---------------- scratch (device globals; allocation-free rule) -------------
__device__ float    g_h[NH*BB*NN*FH];        // per-head hidden  [H][B][N][64]
__device__ float    g_f1[NH*BB*NN];
__device__ float    g_f2[NH*BB*NN];
__device__ unsigned g_adjb[BB*NN*(NN/32)];   // adjacency bitmask [B][N][16]
__device__ float    g_xcat[BB*NN*NH*FH];     // concat(elu(h')) [B][N][512]
__device__ float    g_hout[BB*NN*NC];        // output-layer hidden [B][N][16]
__device__ float    g_f1o[BB*NN];
__device__ float    g_f2o[BB*NN];

// ---------------- 1) pack adjacency to bits (read 33.5MB once) --------------
__global__ void k_pack_adj(const int* __restrict__ adj) {
    int gw   = blockIdx.x * 8 + (threadIdx.x >> 5);   // word index
    int lane = threadIdx.x & 31;
    int m  = ((gw & 15) << 5) | lane;
    int bn = gw >> 4;                                  // b*N + n
    int v  = adj[bn * NN + m] > 0;
    unsigned msk = __ballot_sync(0xffffffffu, v);
    if (lane == 0) g_adjb[gw] = msk;
}

// ---------------- 2) h = x @ W per head  (64n x 64f tile, K=128) ------------
__global__ __launch_bounds__(256) void k_head_gemm(const float* __restrict__ x,
                                                   const float* __restrict__ W) {
    int head = blockIdx.z, b = blockIdx.y, n0 = blockIdx.x * 64;
    __shared__ float xs[64][64];
    __shared__ float ws[64][64];
    int tid = threadIdx.x;
    const float4* xg4 = (const float4*)(x + (b * NN + n0) * NF);   // row stride 32 f4
    const float4* wg4 = (const float4*)(W + head * NF * FH);       // row stride 16 f4
    int tr = tid >> 4, tc = tid & 15;
    float acc[4][4] = {};
    for (int kc = 0; kc < 2; kc++) {
        __syncthreads();
        float4* xs4 = (float4*)&xs[0][0];
        float4* ws4 = (float4*)&ws[0][0];
        #pragma unroll
        for (int i = 0; i < 4; i++) {
            int idx = tid + i * 256;
            xs4[idx] = xg4[(idx >> 4) * 32 + kc * 16 + (idx & 15)];
            ws4[idx] = wg4[(kc * 64 + (idx >> 4)) * 16 + (idx & 15)];
        }
        __syncthreads();
        #pragma unroll 8
        for (int k = 0; k < 64; k++) {
            float av[4];
            #pragma unroll
            for (int i = 0; i < 4; i++) av[i] = xs[tr * 4 + i][k];
            float4 bv = *(const float4*)&ws[k][tc * 4];
            float bvv[4] = {bv.x, bv.y, bv.z, bv.w};
            #pragma unroll
            for (int i = 0; i < 4; i++)
                #pragma unroll
                for (int j = 0; j < 4; j++)
                    acc[i][j] = fmaf(av[i], bvv[j], acc[i][j]);
        }
    }
    #pragma unroll
    for (int i = 0; i < 4; i++) {
        float4 v = make_float4(acc[i][0], acc[i][1], acc[i][2], acc[i][3]);
        *(float4*)&g_h[((head * BB + b) * NN + n0 + tr * 4 + i) * FH + tc * 4] = v;
    }
}

// ---------------- 3) f1/f2 = h . a1 / h . a2  (one warp per row) ------------
__global__ void k_f12(const float* __restrict__ a1h, const float* __restrict__ a2h) {
    int gw   = blockIdx.x * 8 + (threadIdx.x >> 5);   // head*B*N + b*N + n
    int lane = threadIdx.x & 31;
    int head = gw / (BB * NN);
    const float* hp = g_h + gw * FH;
    float v0 = hp[lane], v1 = hp[lane + 32];
    float s1 = v0 * a1h[head * FH + lane] + v1 * a1h[head * FH + lane + 32];
    float s2 = v0 * a2h[head * FH + lane] + v1 * a2h[head * FH + lane + 32];
    #pragma unroll
    for (int o = 16; o; o >>= 1) {
        s1 += __shfl_xor_sync(0xffffffffu, s1, o);
        s2 += __shfl_xor_sync(0xffffffffu, s2, o);
    }
    if (lane == 0) { g_f1[gw] = s1; g_f2[gw] = s2; }
}

// ---------------- 4) fused masked-softmax attention + ELU, write x_cat ------
__global__ __launch_bounds__(256) void k_attn() {
    int head = blockIdx.z, b = blockIdx.y, n0 = blockIdx.x * 64;
    int hb = head * BB + b;
    __shared__ float    f2s[NN];
    __shared__ float    f1s[64];
    __shared__ unsigned adjw[64 * 16];
    __shared__ float    rmx[64], rinv[64];
    __shared__ float    hs[64 * 64];      // 64 m-rows x 64 f
    __shared__ float    ps[64 * 68];      // P tile [row][m], pad 68
    int tid = threadIdx.x;

    for (int i = tid; i < NN; i += 256) f2s[i] = g_f2[hb * NN + i];
    if (tid < 64) f1s[tid] = g_f1[hb * NN + n0 + tid];
    {
        const unsigned* ab = g_adjb + (b * NN + n0) * 16;
        for (int i = tid; i < 1024; i += 256) adjw[i] = ab[i];
    }
    __syncthreads();

    int r = tid >> 2, q = tid & 3;
    float f1v = f1s[r];
    // pass 1a: row max
    float mx = -3e38f;
    for (int m = q; m < NN; m += 4) {
        float z = f1v + f2s[m];
        float e = z > 0.f ? z : ALPHA * z;
        e = ((adjw[(r << 4) + (m >> 5)] >> (m & 31)) & 1u) ? e : NEGINF;
        mx = fmaxf(mx, e);
    }
    mx = fmaxf(mx, __shfl_xor_sync(0xffffffffu, mx, 1));
    mx = fmaxf(mx, __shfl_xor_sync(0xffffffffu, mx, 2));
    // pass 1b: row sum
    float s = 0.f;
    for (int m = q; m < NN; m += 4) {
        float z = f1v + f2s[m];
        float e = z > 0.f ? z : ALPHA * z;
        e = ((adjw[(r << 4) + (m >> 5)] >> (m & 31)) & 1u) ? e : NEGINF;
        s += __expf(e - mx);
    }
    s += __shfl_xor_sync(0xffffffffu, s, 1);
    s += __shfl_xor_sync(0xffffffffu, s, 2);
    if (q == 0) { rmx[r] = mx; rinv[r] = 1.0f / s; }

    float4 acc0 = {0,0,0,0}, acc1 = {0,0,0,0}, acc2 = {0,0,0,0}, acc3 = {0,0,0,0};
    const float4* hg4 = (const float4*)g_h + hb * NN * 16;
    for (int c = 0; c < 8; c++) {
        __syncthreads();
        float4* hs4 = (float4*)hs;
        #pragma unroll
        for (int i = 0; i < 4; i++) hs4[tid + i * 256] = hg4[c * 1024 + tid + i * 256];
        #pragma unroll
        for (int i = 0; i < 16; i++) {
            int idx = tid + i * 256;            // 0..4095
            int r2 = idx >> 6, mloc = idx & 63, m2 = (c << 6) + mloc;
            float z = f1s[r2] + f2s[m2];
            float e = z > 0.f ? z : ALPHA * z;
            e = ((adjw[(r2 << 4) + (m2 >> 5)] >> (m2 & 31)) & 1u) ? e : NEGINF;
            ps[r2 * 68 + mloc] = __expf(e - rmx[r2]) * rinv[r2];
        }
        __syncthreads();
        const float4* hp = (const float4*)hs + (q << 2);
        #pragma unroll 4
        for (int mm = 0; mm < 64; mm++) {
            float p = ps[r * 68 + mm];
            float4 h0 = hp[mm * 16 + 0], h1 = hp[mm * 16 + 1];
            float4 h2 = hp[mm * 16 + 2], h3 = hp[mm * 16 + 3];
            acc0.x = fmaf(p, h0.x, acc0.x); acc0.y = fmaf(p, h0.y, acc0.y);
            acc0.z = fmaf(p, h0.z, acc0.z); acc0.w = fmaf(p, h0.w, acc0.w);
            acc1.x = fmaf(p, h1.x, acc1.x); acc1.y = fmaf(p, h1.y, acc1.y);
            acc1.z = fmaf(p, h1.z, acc1.z); acc1.w = fmaf(p, h1.w, acc1.w);
            acc2.x = fmaf(p, h2.x, acc2.x); acc2.y = fmaf(p, h2.y, acc2.y);
            acc2.z = fmaf(p, h2.z, acc2.z); acc2.w = fmaf(p, h2.w, acc2.w);
            acc3.x = fmaf(p, h3.x, acc3.x); acc3.y = fmaf(p, h3.y, acc3.y);
            acc3.z = fmaf(p, h3.z, acc3.z); acc3.w = fmaf(p, h3.w, acc3.w);
        }
    }
    // ELU + store into concat layout
    float ov[16] = {acc0.x, acc0.y, acc0.z, acc0.w, acc1.x, acc1.y, acc1.z, acc1.w,
                    acc2.x, acc2.y, acc2.z, acc2.w, acc3.x, acc3.y, acc3.z, acc3.w};
    float* op = g_xcat + (b * NN + n0 + r) * (NH * FH) + head * FH + (q << 4);
    #pragma unroll
    for (int j4 = 0; j4 < 4; j4++) {
        float4 v;
        float* vv = (float*)&v;
        #pragma unroll
        for (int jj = 0; jj < 4; jj++) {
            float u = ov[j4 * 4 + jj];
            vv[jj] = u > 0.f ? u : expm1f(u);
        }
        *(float4*)&op[j4 * 4] = v;
    }
}

// ---------------- 5) hout = x_cat @ W_out  (16 rows/block, K=512) -----------
__global__ __launch_bounds__(256) void k_out_gemm(const float* __restrict__ Wout) {
    __shared__ float ws[512 * 16];   // 32KB
    __shared__ float xs[16 * 128];   // 8KB
    int tid = threadIdx.x;
    {
        float4* ws4 = (float4*)ws;
        const float4* wg4 = (const float4*)Wout;
        #pragma unroll
        for (int i = 0; i < 8; i++) ws4[tid + i * 256] = wg4[tid + i * 256];
    }
    int n0 = blockIdx.x * 16;
    const float4* xg4 = (const float4*)g_xcat + n0 * 128;   // row stride 128 f4
    int lr = tid >> 4, c = tid & 15;
    float acc = 0.f;
    for (int kc = 0; kc < 4; kc++) {
        __syncthreads();
        float4* xs4 = (float4*)xs;
        #pragma unroll
        for (int i = 0; i < 2; i++) {
            int idx = tid + i * 256;            // 0..511
            int row = idx >> 5, col = idx & 31;
            xs4[idx] = xg4[row * 128 + kc * 32 + col];
        }
        __syncthreads();
        #pragma unroll 8
        for (int kk = 0; kk < 128; kk++)
            acc = fmaf(xs[lr * 128 + kk], ws[(kc * 128 + kk) * 16 + c], acc);
    }
    g_hout[(n0 + lr) * 16 + c] = acc;
}

// ---------------- 6) f1o/f2o ------------------------------------------------
__global__ void k_f12o(const float* __restrict__ a1o, const float* __restrict__ a2o) {
    int bn = blockIdx.x * 256 + threadIdx.x;
    const float* hp = g_hout + bn * 16;
    float s1 = 0.f, s2 = 0.f;
    #pragma unroll
    for (int c = 0; c < 16; c++) { s1 = fmaf(hp[c], a1o[c], s1); s2 = fmaf(hp[c], a2o[c], s2); }
    g_f1o[bn] = s1; g_f2o[bn] = s2;
}

// ---------------- 7) output attention (F=16, no ELU) ------------------------
__global__ __launch_bounds__(256) void k_attn_out(float* __restrict__ out) {
    int b = blockIdx.y, n0 = blockIdx.x * 64;
    __shared__ float    f2s[NN];
    __shared__ float    f1s[64];
    __shared__ unsigned adjw[64 * 16];
    __shared__ float    rmx[64], rinv[64];
    __shared__ float    hs[64 * 16];
    __shared__ float    ps[64 * 68];
    int tid = threadIdx.x;

    for (int i = tid; i < NN; i += 256) f2s[i] = g_f2o[b * NN + i];
    if (tid < 64) f1s[tid] = g_f1o[b * NN + n0 + tid];
    {
        const unsigned* ab = g_adjb + (b * NN + n0) * 16;
        for (int i = tid; i < 1024; i += 256) adjw[i] = ab[i];
    }
    __syncthreads();

    int r = tid >> 2, q = tid & 3;
    float f1v = f1s[r];
    float mx = -3e38f;
    for (int m = q; m < NN; m += 4) {
        float z = f1v + f2s[m];
        float e = z > 0.f ? z : ALPHA * z;
        e = ((adjw[(r << 4) + (m >> 5)] >> (m & 31)) & 1u) ? e : NEGINF;
        mx = fmaxf(mx, e);
    }
    mx = fmaxf(mx, __shfl_xor_sync(0xffffffffu, mx, 1));
    mx = fmaxf(mx, __shfl_xor_sync(0xffffffffu, mx, 2));
    float s = 0.f;
    for (int m = q; m < NN; m += 4) {
        float z = f1v + f2s[m];
        float e = z > 0.f ? z : ALPHA * z;
        e = ((adjw[(r << 4) + (m >> 5)] >> (m & 31)) & 1u) ? e : NEGINF;
        s += __expf(e - mx);
    }
    s += __shfl_xor_sync(0xffffffffu, s, 1);
    s += __shfl_xor_sync(0xffffffffu, s, 2);
    if (q == 0) { rmx[r] = mx; rinv[r] = 1.0f / s; }

    float4 acc = {0, 0, 0, 0};
    const float4* hg4 = (const float4*)g_hout + b * NN * 4;   // 4 f4 per m-row
    for (int c = 0; c < 8; c++) {
        __syncthreads();
        ((float4*)hs)[tid] = hg4[c * 256 + tid];
        #pragma unroll
        for (int i = 0; i < 16; i++) {
            int idx = tid + i * 256;
            int r2 = idx >> 6, mloc = idx & 63, m2 = (c << 6) + mloc;
            float z = f1s[r2] + f2s[m2];
            float e = z > 0.f ? z : ALPHA * z;
            e = ((adjw[(r2 << 4) + (m2 >> 5)] >> (m2 & 31)) & 1u) ? e : NEGINF;
            ps[r2 * 68 + mloc] = __expf(e - rmx[r2]) * rinv[r2];
        }
        __syncthreads();
        #pragma unroll 8
        for (int mm = 0; mm < 64; mm++) {
            float p = ps[r * 68 + mm];
            float4 hv = ((const float4*)hs)[mm * 4 + q];
            acc.x = fmaf(p, hv.x, acc.x); acc.y = fmaf(p, hv.y, acc.y);
            acc.z = fmaf(p, hv.z, acc.z); acc.w = fmaf(p, hv.w, acc.w);
        }
    }
    *(float4*)&out[(b * NN + n0 + r) * NC + (q << 2)] = acc;
}

// ---------------- launch ----------------------------------------------------
extern "C" void kernel_launch(void* const* d_in, const int* in_sizes, int n_in,
                              void* d_out, int out_size) {
    const float* x   = (const float*)d_in[0];
    const int*   adj = (const int*)  d_in[1];
    const float* Wh  = (const float*)d_in[2];
    const float* a1h = (const float*)d_in[3];
    const float* a2h = (const float*)d_in[4];
    const float* Wo  = (const float*)d_in[5];
    const float* a1o = (const float*)d_in[6];
    const float* a2o = (const float*)d_in[7];
    float* out = (float*)d_out;

    k_pack_adj <<<BB * NN * 16 / 8, 256>>>(adj);
    k_head_gemm<<<dim3(8, BB, NH), 256>>>(x, Wh);
    k_f12      <<<NH * BB * NN / 8, 256>>>(a1h, a2h);
    k_attn     <<<dim3(8, BB, NH), 256>>>();
    k_out_gemm <<<BB * NN / 16, 256>>>(Wo);
    k_f12o     <<<BB * NN / 256, 256>>>(a1o, a2o);
    k_attn_out <<<dim3(8, BB), 256>>>(out);
}

// round 4
// speedup vs baseline: 2.8959x; 2.8959x over previous
#include <cuda_runtime.h>
#include <math.h>

#define BB 32
#define NN 512
#define NF 128
#define FH 64
#define NH 8
#define NC 16
#define ALPHA 0.2f
#define NEGINF -9e15f

// ---------------- scratch (device globals; allocation-free rule) -------------
__device__ float    g_h[NH*BB*NN*FH];        // per-head hidden  [H][B][N][64]
__device__ float    g_f1[NH*BB*NN];
__device__ float    g_f2[NH*BB*NN];
__device__ unsigned g_adjb[BB*NN*(NN/32)];   // adjacency bitmask [B][N][16]
__device__ float    g_xcat[BB*NN*NH*FH];     // concat(elu(h')) [B][N][512]
__device__ float    g_hout[BB*NN*NC];        // output-layer hidden [B][N][16]
__device__ float    g_f1o[BB*NN];
__device__ float    g_f2o[BB*NN];

// ---------------- packed f32x2 helpers ---------------------------------------
__device__ __forceinline__ unsigned long long fma2(unsigned long long a,
                                                   unsigned long long b,
                                                   unsigned long long c) {
    unsigned long long d;
    asm("fma.rn.f32x2 %0, %1, %2, %3;" : "=l"(d) : "l"(a), "l"(b), "l"(c));
    return d;
}
__device__ __forceinline__ unsigned long long pack2(float x) {
    unsigned long long d;
    asm("mov.b64 %0, {%1, %1};" : "=l"(d) : "r"(__float_as_uint(x)));
    return d;
}
__device__ __forceinline__ float lo2(unsigned long long v) {
    return __uint_as_float((unsigned)(v & 0xffffffffull));
}
__device__ __forceinline__ float hi2(unsigned long long v) {
    return __uint_as_float((unsigned)(v >> 32));
}

// ---------------- 1) pack adjacency to bits (read 33.5MB once) --------------
__global__ void k_pack_adj(const int* __restrict__ adj) {
    int gw   = blockIdx.x * 8 + (threadIdx.x >> 5);   // word index
    int lane = threadIdx.x & 31;
    int m  = ((gw & 15) << 5) | lane;
    int bn = gw >> 4;                                  // b*N + n
    int v  = adj[bn * NN + m] > 0;
    unsigned msk = __ballot_sync(0xffffffffu, v);
    if (lane == 0) g_adjb[gw] = msk;
}

// ---------------- 2) h = x @ W per head  (64n x 64f tile, K=128) ------------
__global__ __launch_bounds__(256) void k_head_gemm(const float* __restrict__ x,
                                                   const float* __restrict__ W) {
    int head = blockIdx.z, b = blockIdx.y, n0 = blockIdx.x * 64;
    __shared__ float xs[64][64];
    __shared__ float ws[64][64];
    int tid = threadIdx.x;
    const float4* xg4 = (const float4*)(x + (b * NN + n0) * NF);   // row stride 32 f4
    const float4* wg4 = (const float4*)(W + head * NF * FH);       // row stride 16 f4
    int tr = tid >> 4, tc = tid & 15;
    float acc[4][4] = {};
    for (int kc = 0; kc < 2; kc++) {
        __syncthreads();
        float4* xs4 = (float4*)&xs[0][0];
        float4* ws4 = (float4*)&ws[0][0];
        #pragma unroll
        for (int i = 0; i < 4; i++) {
            int idx = tid + i * 256;
            xs4[idx] = xg4[(idx >> 4) * 32 + kc * 16 + (idx & 15)];
            ws4[idx] = wg4[(kc * 64 + (idx >> 4)) * 16 + (idx & 15)];
        }
        __syncthreads();
        #pragma unroll 8
        for (int k = 0; k < 64; k++) {
            float av[4];
            #pragma unroll
            for (int i = 0; i < 4; i++) av[i] = xs[tr * 4 + i][k];
            float4 bv = *(const float4*)&ws[k][tc * 4];
            float bvv[4] = {bv.x, bv.y, bv.z, bv.w};
            #pragma unroll
            for (int i = 0; i < 4; i++)
                #pragma unroll
                for (int j = 0; j < 4; j++)
                    acc[i][j] = fmaf(av[i], bvv[j], acc[i][j]);
        }
    }
    #pragma unroll
    for (int i = 0; i < 4; i++) {
        float4 v = make_float4(acc[i][0], acc[i][1], acc[i][2], acc[i][3]);
        *(float4*)&g_h[((head * BB + b) * NN + n0 + tr * 4 + i) * FH + tc * 4] = v;
    }
}

// ---------------- 3) f1/f2 = h . a1 / h . a2  (one warp per row) ------------
__global__ void k_f12(const float* __restrict__ a1h, const float* __restrict__ a2h) {
    int gw   = blockIdx.x * 8 + (threadIdx.x >> 5);   // head*B*N + b*N + n
    int lane = threadIdx.x & 31;
    int head = gw / (BB * NN);
    const float* hp = g_h + gw * FH;
    float v0 = hp[lane], v1 = hp[lane + 32];
    float s1 = v0 * a1h[head * FH + lane] + v1 * a1h[head * FH + lane + 32];
    float s2 = v0 * a2h[head * FH + lane] + v1 * a2h[head * FH + lane + 32];
    #pragma unroll
    for (int o = 16; o; o >>= 1) {
        s1 += __shfl_xor_sync(0xffffffffu, s1, o);
        s2 += __shfl_xor_sync(0xffffffffu, s2, o);
    }
    if (lane == 0) { g_f1[gw] = s1; g_f2[gw] = s2; }
}

// ---------------- 4) fused masked-softmax attention + ELU -------------------
// 128 threads, tile = 128 rows x 64 f. m processed in chunks of 32.
// Each thread owns one row's softmax stats (registers) and an 8x8 output
// micro-tile in the P*h product, computed with packed f32x2 FMAs.
#define PST 132   // padded stride for P^T tile [32][PST]
__global__ __launch_bounds__(128) void k_attn() {
    int head = blockIdx.z, b = blockIdx.y, n0 = blockIdx.x * 128;
    int hb = head * BB + b;
    __shared__ float    f2s[NN];
    __shared__ float    f1s[128];
    __shared__ unsigned adjw[128 * 16];
    __shared__ float    hs[32 * 64];       // h chunk [mloc][f]
    __shared__ float    pst[32 * PST];     // P^T chunk [mloc][row]
    int tid = threadIdx.x;

    #pragma unroll
    for (int i = 0; i < 4; i++) f2s[tid + i * 128] = g_f2[hb * NN + tid + i * 128];
    f1s[tid] = g_f1[hb * NN + n0 + tid];
    {
        const unsigned* ab = g_adjb + (b * NN + n0) * 16;
        #pragma unroll
        for (int i = 0; i < 16; i++) adjw[tid + i * 128] = ab[tid + i * 128];
    }
    __syncthreads();

    // ---- per-row softmax stats, fully in registers (thread = row) ----
    float f1v = f1s[tid];
    const unsigned* aw = adjw + tid * 16;
    float mx = -3e38f;
    for (int w = 0; w < 16; w++) {
        unsigned word = aw[w];
        #pragma unroll
        for (int j = 0; j < 32; j++) {
            float z = f1v + f2s[w * 32 + j];
            float e = fmaxf(z, ALPHA * z);
            e = ((word >> j) & 1u) ? e : NEGINF;
            mx = fmaxf(mx, e);
        }
    }
    float s = 0.f;
    for (int w = 0; w < 16; w++) {
        unsigned word = aw[w];
        #pragma unroll
        for (int j = 0; j < 32; j++) {
            float z = f1v + f2s[w * 32 + j];
            float e = fmaxf(z, ALPHA * z);
            e = ((word >> j) & 1u) ? e : NEGINF;
            s += __expf(e - mx);
        }
    }
    float rinv = 1.0f / s;

    // ---- main loop over 16 m-chunks of 32 ----
    int rg = tid >> 3, cg = tid & 7;           // 16 row-groups x 8 col-groups
    unsigned long long acc[8][4];
    #pragma unroll
    for (int i = 0; i < 8; i++)
        #pragma unroll
        for (int j = 0; j < 4; j++) acc[i][j] = 0ull;

    const float4* hg4 = (const float4*)g_h + hb * NN * 16;
    for (int c = 0; c < 16; c++) {
        __syncthreads();
        // load h chunk [32 rows x 64 f]
        {
            float4* hs4 = (float4*)hs;
            #pragma unroll
            for (int i = 0; i < 4; i++) {
                int idx = tid + i * 128;           // 0..511
                hs4[idx] = hg4[(c * 32 + (idx >> 4)) * 16 + (idx & 15)];
            }
        }
        // compute P^T chunk: thread = row, loop over 32 m
        {
            unsigned word = aw[c];
            #pragma unroll
            for (int mloc = 0; mloc < 32; mloc++) {
                float z = f1v + f2s[c * 32 + mloc];
                float e = fmaxf(z, ALPHA * z);
                e = ((word >> mloc) & 1u) ? e : NEGINF;
                pst[mloc * PST + tid] = __expf(e - mx) * rinv;
            }
        }
        __syncthreads();
        // 8x8 micro-tile GEMM on the chunk (f32x2 packed FMAs)
        #pragma unroll 4
        for (int mm = 0; mm < 32; mm++) {
            const float* pr = &pst[mm * PST + rg * 8];
            float4 pa = *(const float4*)pr;
            float4 pb = *(const float4*)(pr + 4);
            const ulonglong2* hp2 = (const ulonglong2*)&hs[mm * 64 + cg * 8];
            ulonglong2 hA = hp2[0], hB = hp2[1];
            unsigned long long pp[8];
            pp[0] = pack2(pa.x); pp[1] = pack2(pa.y); pp[2] = pack2(pa.z); pp[3] = pack2(pa.w);
            pp[4] = pack2(pb.x); pp[5] = pack2(pb.y); pp[6] = pack2(pb.z); pp[7] = pack2(pb.w);
            #pragma unroll
            for (int i = 0; i < 8; i++) {
                acc[i][0] = fma2(pp[i], hA.x, acc[i][0]);
                acc[i][1] = fma2(pp[i], hA.y, acc[i][1]);
                acc[i][2] = fma2(pp[i], hB.x, acc[i][2]);
                acc[i][3] = fma2(pp[i], hB.y, acc[i][3]);
            }
        }
    }

    // ---- ELU + store into concat layout ----
    #pragma unroll
    for (int i = 0; i < 8; i++) {
        float ov[8];
        #pragma unroll
        for (int j = 0; j < 4; j++) { ov[j * 2] = lo2(acc[i][j]); ov[j * 2 + 1] = hi2(acc[i][j]); }
        #pragma unroll
        for (int j = 0; j < 8; j++) { float u = ov[j]; ov[j] = u > 0.f ? u : expm1f(u); }
        float* op = g_xcat + (b * NN + n0 + rg * 8 + i) * (NH * FH) + head * FH + cg * 8;
        *(float4*)&op[0] = make_float4(ov[0], ov[1], ov[2], ov[3]);
        *(float4*)&op[4] = make_float4(ov[4], ov[5], ov[6], ov[7]);
    }
}

// ---------------- 5) hout = x_cat @ W_out  (16 rows/block, K=512) -----------
__global__ __launch_bounds__(256) void k_out_gemm(const float* __restrict__ Wout) {
    __shared__ float ws[512 * 16];   // 32KB
    __shared__ float xs[16 * 128];   // 8KB
    int tid = threadIdx.x;
    {
        float4* ws4 = (float4*)ws;
        const float4* wg4 = (const float4*)Wout;
        #pragma unroll
        for (int i = 0; i < 8; i++) ws4[tid + i * 256] = wg4[tid + i * 256];
    }
    int n0 = blockIdx.x * 16;
    const float4* xg4 = (const float4*)g_xcat + n0 * 128;   // row stride 128 f4
    int lr = tid >> 4, c = tid & 15;
    float acc = 0.f;
    for (int kc = 0; kc < 4; kc++) {
        __syncthreads();
        float4* xs4 = (float4*)xs;
        #pragma unroll
        for (int i = 0; i < 2; i++) {
            int idx = tid + i * 256;            // 0..511
            int row = idx >> 5, col = idx & 31;
            xs4[idx] = xg4[row * 128 + kc * 32 + col];
        }
        __syncthreads();
        #pragma unroll 8
        for (int kk = 0; kk < 128; kk++)
            acc = fmaf(xs[lr * 128 + kk], ws[(kc * 128 + kk) * 16 + c], acc);
    }
    g_hout[(n0 + lr) * 16 + c] = acc;
}

// ---------------- 6) f1o/f2o ------------------------------------------------
__global__ void k_f12o(const float* __restrict__ a1o, const float* __restrict__ a2o) {
    int bn = blockIdx.x * 256 + threadIdx.x;
    const float* hp = g_hout + bn * 16;
    float s1 = 0.f, s2 = 0.f;
    #pragma unroll
    for (int c = 0; c < 16; c++) { s1 = fmaf(hp[c], a1o[c], s1); s2 = fmaf(hp[c], a2o[c], s2); }
    g_f1o[bn] = s1; g_f2o[bn] = s2;
}

// ---------------- 7) output attention (F=16, no ELU) ------------------------
__global__ __launch_bounds__(256) void k_attn_out(float* __restrict__ out) {
    int b = blockIdx.y, n0 = blockIdx.x * 64;
    __shared__ float    f2s[NN];
    __shared__ float    f1s[64];
    __shared__ unsigned adjw[64 * 16];
    __shared__ float    rmx[64], rinv[64];
    __shared__ float    hs[64 * 16];
    __shared__ float    ps[64 * 68];
    int tid = threadIdx.x;

    for (int i = tid; i < NN; i += 256) f2s[i] = g_f2o[b * NN + i];
    if (tid < 64) f1s[tid] = g_f1o[b * NN + n0 + tid];
    {
        const unsigned* ab = g_adjb + (b * NN + n0) * 16;
        for (int i = tid; i < 1024; i += 256) adjw[i] = ab[i];
    }
    __syncthreads();

    int r = tid >> 2, q = tid & 3;
    float f1v = f1s[r];
    float mx = -3e38f;
    for (int m = q; m < NN; m += 4) {
        float z = f1v + f2s[m];
        float e = fmaxf(z, ALPHA * z);
        e = ((adjw[(r << 4) + (m >> 5)] >> (m & 31)) & 1u) ? e : NEGINF;
        mx = fmaxf(mx, e);
    }
    mx = fmaxf(mx, __shfl_xor_sync(0xffffffffu, mx, 1));
    mx = fmaxf(mx, __shfl_xor_sync(0xffffffffu, mx, 2));
    float s = 0.f;
    for (int m = q; m < NN; m += 4) {
        float z = f1v + f2s[m];
        float e = fmaxf(z, ALPHA * z);
        e = ((adjw[(r << 4) + (m >> 5)] >> (m & 31)) & 1u) ? e : NEGINF;
        s += __expf(e - mx);
    }
    s += __shfl_xor_sync(0xffffffffu, s, 1);
    s += __shfl_xor_sync(0xffffffffu, s, 2);
    if (q == 0) { rmx[r] = mx; rinv[r] = 1.0f / s; }

    float4 acc = {0, 0, 0, 0};
    const float4* hg4 = (const float4*)g_hout + b * NN * 4;   // 4 f4 per m-row
    for (int c = 0; c < 8; c++) {
        __syncthreads();
        ((float4*)hs)[tid] = hg4[c * 256 + tid];
        #pragma unroll
        for (int i = 0; i < 16; i++) {
            int idx = tid + i * 256;
            int r2 = idx >> 6, mloc = idx & 63, m2 = (c << 6) + mloc;
            float z = f1s[r2] + f2s[m2];
            float e = fmaxf(z, ALPHA * z);
            e = ((adjw[(r2 << 4) + (m2 >> 5)] >> (m2 & 31)) & 1u) ? e : NEGINF;
            ps[r2 * 68 + mloc] = __expf(e - rmx[r2]) * rinv[r2];
        }
        __syncthreads();
        #pragma unroll 8
        for (int mm = 0; mm < 64; mm++) {
            float p = ps[r * 68 + mm];
            float4 hv = ((const float4*)hs)[mm * 4 + q];
            acc.x = fmaf(p, hv.x, acc.x); acc.y = fmaf(p, hv.y, acc.y);
            acc.z = fmaf(p, hv.z, acc.z); acc.w = fmaf(p, hv.w, acc.w);
        }
    }
    *(float4*)&out[(b * NN + n0 + r) * NC + (q << 2)] = acc;
}

// ---------------- launch ----------------------------------------------------
extern "C" void kernel_launch(void* const* d_in, const int* in_sizes, int n_in,
                              void* d_out, int out_size) {
    const float* x   = (const float*)d_in[0];
    const int*   adj = (const int*)  d_in[1];
    const float* Wh  = (const float*)d_in[2];
    const float* a1h = (const float*)d_in[3];
    const float* a2h = (const float*)d_in[4];
    const float* Wo  = (const float*)d_in[5];
    const float* a1o = (const float*)d_in[6];
    const float* a2o = (const float*)d_in[7];
    float* out = (float*)d_out;

    k_pack_adj <<<BB * NN * 16 / 8, 256>>>(adj);
    k_head_gemm<<<dim3(8, BB, NH), 256>>>(x, Wh);
    k_f12      <<<NH * BB * NN / 8, 256>>>(a1h, a2h);
    k_attn     <<<dim3(4, BB, NH), 128>>>();
    k_out_gemm <<<BB * NN / 16, 256>>>(Wo);
    k_f12o     <<<BB * NN / 256, 256>>>(a1o, a2o);
    k_attn_out <<<dim3(8, BB), 256>>>(out);
}

// round 6
// speedup vs baseline: 3.8857x; 1.3418x over previous
#include <cuda_runtime.h>
#include <cuda_bf16.h>
#include <math.h>
#include <stdint.h>

#define BB 32
#define NN 512
#define NF 128
#define FH 64
#define NH 8
#define NC 16
#define ALPHA 0.2f

// ---------------- scratch (device globals; allocation-free rule) -------------
__device__ float          g_f1[NH*BB*NN];
__device__ float          g_f2[NH*BB*NN];
__device__ unsigned       g_adjb[BB*NN*(NN/32)];    // adjacency bitmask [B][N][16]
__device__ __nv_bfloat16  g_hT_hi[NH*BB*FH*NN];     // h^T hi [H*B][f][m]
__device__ __nv_bfloat16  g_hT_lo[NH*BB*FH*NN];     // h^T lo
__device__ float          g_xcat[BB*NN*NH*FH];      // concat(elu(h')) [B][N][512]
__device__ float          g_hout[BB*NN*NC];
__device__ float          g_f1o[BB*NN];
__device__ float          g_f2o[BB*NN];

// ---------------- helpers ----------------------------------------------------
__device__ __forceinline__ uint32_t smem_u32(const void* p) {
    uint32_t a;
    asm("{ .reg .u64 t; cvta.to.shared.u64 t, %1; cvt.u32.u64 %0, t; }"
        : "=r"(a) : "l"(p));
    return a;
}
#define SWZ(o) ((o) ^ ((((unsigned)(o)) >> 3) & 0x70))

__device__ __forceinline__ unsigned packbf2(__nv_bfloat16 a, __nv_bfloat16 b) {
    __nv_bfloat162 p; p.x = a; p.y = b;
    return *(unsigned*)&p;
}

#define LDSM_X4(r0, r1, r2, r3, addr) \
    asm volatile("ldmatrix.sync.aligned.m8n8.x4.shared.b16 {%0,%1,%2,%3}, [%4];" \
        : "=r"(r0), "=r"(r1), "=r"(r2), "=r"(r3) : "r"(addr))

#define MMA16816(c, a0, a1, a2, a3, b0, b1) \
    asm volatile("mma.sync.aligned.m16n8k16.row.col.f32.bf16.bf16.f32 " \
        "{%0,%1,%2,%3}, {%4,%5,%6,%7}, {%8,%9}, {%0,%1,%2,%3};" \
        : "+f"((c)[0]), "+f"((c)[1]), "+f"((c)[2]), "+f"((c)[3]) \
        : "r"(a0), "r"(a1), "r"(a2), "r"(a3), "r"(b0), "r"(b1))

// ---------------- 1) pack adjacency to bits ---------------------------------
__global__ void k_pack_adj(const int* __restrict__ adj) {
    int gw   = blockIdx.x * 8 + (threadIdx.x >> 5);
    int lane = threadIdx.x & 31;
    int m  = ((gw & 15) << 5) | lane;
    int bn = gw >> 4;
    int v  = adj[bn * NN + m] > 0;
    unsigned msk = __ballot_sync(0xffffffffu, v);
    if (lane == 0) g_adjb[gw] = msk;
}

// ---------------- 2) h = x @ W per head + f1/f2 + bf16 h^T hi/lo ------------
__global__ __launch_bounds__(256) void k_head_gemm(const float* __restrict__ x,
                                                   const float* __restrict__ W,
                                                   const float* __restrict__ a1h,
                                                   const float* __restrict__ a2h) {
    int head = blockIdx.z, b = blockIdx.y, n0 = blockIdx.x * 64;
    int hb = head * BB + b;
    __shared__ float pool[8192];                 // 32KB: xs(16K) + ws(16K), reused as hstage
    float* xs = pool;                            // [64][64]
    float* ws = pool + 4096;                     // [64][64]
    int tid = threadIdx.x;
    const float4* xg4 = (const float4*)(x + (b * NN + n0) * NF);
    const float4* wg4 = (const float4*)(W + head * NF * FH);
    int tr = tid >> 4, tc = tid & 15;
    float acc[4][4] = {};
    for (int kc = 0; kc < 2; kc++) {
        __syncthreads();
        float4* xs4 = (float4*)xs;
        float4* ws4 = (float4*)ws;
        #pragma unroll
        for (int i = 0; i < 4; i++) {
            int idx = tid + i * 256;
            xs4[idx] = xg4[(idx >> 4) * 32 + kc * 16 + (idx & 15)];
            ws4[idx] = wg4[(kc * 64 + (idx >> 4)) * 16 + (idx & 15)];
        }
        __syncthreads();
        #pragma unroll 8
        for (int k = 0; k < 64; k++) {
            float av[4];
            #pragma unroll
            for (int i = 0; i < 4; i++) av[i] = xs[(tr * 4 + i) * 64 + k];
            float4 bv = *(const float4*)&ws[k * 64 + tc * 4];
            float bvv[4] = {bv.x, bv.y, bv.z, bv.w};
            #pragma unroll
            for (int i = 0; i < 4; i++)
                #pragma unroll
                for (int j = 0; j < 4; j++)
                    acc[i][j] = fmaf(av[i], bvv[j], acc[i][j]);
        }
    }
    // stage h tile [64 n][65 pad] into pool (reuse), then epilogue
    __syncthreads();
    float* hstage = pool;                        // 64*65 = 4160 floats
    #pragma unroll
    for (int i = 0; i < 4; i++)
        #pragma unroll
        for (int j = 0; j < 4; j++)
            hstage[(tr * 4 + i) * 65 + tc * 4 + j] = acc[i][j];
    __syncthreads();
    // f1/f2: 4 threads per row
    {
        int r = tid >> 2, qq = tid & 3;
        float s1 = 0.f, s2 = 0.f;
        #pragma unroll
        for (int k = 0; k < 16; k++) {
            int f = qq * 16 + k;
            float v = hstage[r * 65 + f];
            s1 = fmaf(v, a1h[head * FH + f], s1);
            s2 = fmaf(v, a2h[head * FH + f], s2);
        }
        s1 += __shfl_xor_sync(0xffffffffu, s1, 1);
        s1 += __shfl_xor_sync(0xffffffffu, s1, 2);
        s2 += __shfl_xor_sync(0xffffffffu, s2, 1);
        s2 += __shfl_xor_sync(0xffffffffu, s2, 2);
        if (qq == 0) { g_f1[hb * NN + n0 + r] = s1; g_f2[hb * NN + n0 + r] = s2; }
    }
    // h^T hi/lo bf16: thread -> (f = tid>>2, 16 n values)
    {
        int f = tid >> 2, nq = tid & 3;
        unsigned hw[8], lw[8];
        #pragma unroll
        for (int k2 = 0; k2 < 8; k2++) {
            float v0 = hstage[(nq * 16 + 2 * k2)     * 65 + f];
            float v1 = hstage[(nq * 16 + 2 * k2 + 1) * 65 + f];
            __nv_bfloat16 h0 = __float2bfloat16(v0), h1 = __float2bfloat16(v1);
            __nv_bfloat16 l0 = __float2bfloat16(v0 - __bfloat162float(h0));
            __nv_bfloat16 l1 = __float2bfloat16(v1 - __bfloat162float(h1));
            hw[k2] = packbf2(h0, h1);
            lw[k2] = packbf2(l0, l1);
        }
        size_t base = ((size_t)(hb * FH + f)) * NN + n0 + nq * 16;
        *(uint4*)(g_hT_hi + base)     = make_uint4(hw[0], hw[1], hw[2], hw[3]);
        *(uint4*)(g_hT_hi + base + 8) = make_uint4(hw[4], hw[5], hw[6], hw[7]);
        *(uint4*)(g_hT_lo + base)     = make_uint4(lw[0], lw[1], lw[2], lw[3]);
        *(uint4*)(g_hT_lo + base + 8) = make_uint4(lw[4], lw[5], lw[6], lw[7]);
    }
}

// ---------------- 3) tensor-core fused attention (mma.sync bf16x3) ----------
// Block = (head, b, 128-row tile), 256 threads = 8 warps; warp w owns rows
// [w*16, w*16+16). Single-pass unnormalized softmax: accumulate exp(e)*h via
// HMMA with fp32 accumulators, scale by 1/s in the epilogue + ELU.
#define P_HI_OFF  0          // [128][64] bf16 SW128 rows = 16KB
#define P_LO_OFF  16384
#define BH_OFF    32768      // h^T chunk [64 f][64 m] bf16 = 8KB
#define BL_OFF    40960
#define F2S_OFF   49152      // 512 floats
#define SROW_OFF  51200      // 128 floats
#define SMEM_ATTN 51712

__global__ __launch_bounds__(256) void k_attn() {
    extern __shared__ char sm[];
    uint32_t smb = smem_u32(sm);
    float* f2s  = (float*)(sm + F2S_OFF);
    float* srow = (float*)(sm + SROW_OFF);
    int head = blockIdx.z, b = blockIdx.y, n0 = blockIdx.x * 128;
    int hb = head * BB + b;
    int tid = threadIdx.x, warp = tid >> 5, lane = tid & 31;

    #pragma unroll
    for (int i = 0; i < 2; i++) f2s[tid + i * 256] = g_f2[hb * NN + tid + i * 256];
    int r = tid >> 1, half = tid & 1;
    float f1v = g_f1[hb * NN + n0 + r];
    const unsigned* gadj_row = g_adjb + (size_t)(b * NN + n0 + r) * 16;

    float s = 0.f;
    float c[8][4];
    #pragma unroll
    for (int i = 0; i < 8; i++)
        #pragma unroll
        for (int j = 0; j < 4; j++) c[i][j] = 0.f;

    // ldmatrix lane geometry (shared by A and B)
    int q = lane >> 3, ri = lane & 7;
    int arow = warp * 16 + ((q & 1) << 3) + ri;      // A row for this lane
    int frow = ((q & 1) << 3) + ri;                  // B f-row base
    int akb  = (q >> 1) << 4;                        // k-byte offset 0/16

    const uint4* shp = (const uint4*)g_hT_hi + (size_t)hb * FH * (NN / 8);
    const uint4* slp = (const uint4*)g_hT_lo + (size_t)hb * FH * (NN / 8);

    for (int ch = 0; ch < 8; ch++) {
        __syncthreads();
        // ---- produce P chunk [128 rows][64 m] hi/lo (thread = row-half, 32 m) ----
        {
            unsigned word = gadj_row[ch * 2 + half];
            const float* f2c = f2s + ch * 64 + half * 32;
            #pragma unroll
            for (int g = 0; g < 4; g++) {
                unsigned hh[4], ll[4];
                #pragma unroll
                for (int jj = 0; jj < 4; jj++) {
                    float v2[2];
                    #pragma unroll
                    for (int t = 0; t < 2; t++) {
                        int kk = g * 8 + jj * 2 + t;
                        float z = f1v + f2c[kk];
                        float e = fmaxf(z, ALPHA * z);
                        float val = ((word >> kk) & 1u) ? __expf(e) : 0.f;
                        s += val;
                        v2[t] = val;
                    }
                    __nv_bfloat16 h0 = __float2bfloat16(v2[0]), h1 = __float2bfloat16(v2[1]);
                    __nv_bfloat16 l0 = __float2bfloat16(v2[0] - __bfloat162float(h0));
                    __nv_bfloat16 l1 = __float2bfloat16(v2[1] - __bfloat162float(h1));
                    hh[jj] = packbf2(h0, h1);
                    ll[jj] = packbf2(l0, l1);
                }
                uint32_t off = SWZ(r * 128 + half * 64 + g * 16);
                *(uint4*)(sm + P_HI_OFF + off) = make_uint4(hh[0], hh[1], hh[2], hh[3]);
                *(uint4*)(sm + P_LO_OFF + off) = make_uint4(ll[0], ll[1], ll[2], ll[3]);
            }
        }
        // ---- load h^T chunk [64 f][64 m] hi/lo ----
        #pragma unroll
        for (int i = 0; i < 2; i++) {
            int idx = tid + i * 256;               // 0..511
            int f = idx >> 3, jj = idx & 7;
            uint32_t off = SWZ(f * 128 + jj * 16);
            *(uint4*)(sm + BH_OFF + off) = shp[f * 64 + ch * 8 + jj];
            *(uint4*)(sm + BL_OFF + off) = slp[f * 64 + ch * 8 + jj];
        }
        __syncthreads();
        // ---- HMMA: 4 k-steps of 16, 8 n-tiles, 3 split terms ----
        #pragma unroll
        for (int kc = 0; kc < 4; kc++) {
            uint32_t ao = SWZ(arow * 128 + kc * 32 + akb);
            uint32_t ah[4], al[4];
            LDSM_X4(ah[0], ah[1], ah[2], ah[3], smb + P_HI_OFF + ao);
            LDSM_X4(al[0], al[1], al[2], al[3], smb + P_LO_OFF + ao);
            #pragma unroll
            for (int np = 0; np < 4; np++) {
                uint32_t bo = SWZ((np * 16 + frow) * 128 + kc * 32 + akb);
                uint32_t bh[4], bl[4];
                LDSM_X4(bh[0], bh[1], bh[2], bh[3], smb + BH_OFF + bo);
                LDSM_X4(bl[0], bl[1], bl[2], bl[3], smb + BL_OFF + bo);
                MMA16816(c[np*2],   ah[0], ah[1], ah[2], ah[3], bh[0], bh[2]);
                MMA16816(c[np*2],   ah[0], ah[1], ah[2], ah[3], bl[0], bl[2]);
                MMA16816(c[np*2],   al[0], al[1], al[2], al[3], bh[0], bh[2]);
                MMA16816(c[np*2+1], ah[0], ah[1], ah[2], ah[3], bh[1], bh[3]);
                MMA16816(c[np*2+1], ah[0], ah[1], ah[2], ah[3], bl[1], bl[3]);
                MMA16816(c[np*2+1], al[0], al[1], al[2], al[3], bh[1], bh[3]);
            }
        }
    }

    // ---- row sums -> SMEM ----
    s += __shfl_xor_sync(0xffffffffu, s, 1);
    if (half == 0) srow[r] = s;
    __syncthreads();

    // ---- epilogue: scale by 1/s, ELU, write concat ----
    int g4 = lane >> 2, t4 = lane & 3;
    int row0 = warp * 16 + g4;
    float rinv0 = 1.0f / srow[row0];
    float rinv1 = 1.0f / srow[row0 + 8];
    float* op0 = g_xcat + (size_t)(b * NN + n0 + row0) * (NH * FH) + head * FH;
    float* op1 = op0 + 8 * (NH * FH);
    #pragma unroll
    for (int np = 0; np < 8; np++) {
        int col = np * 8 + t4 * 2;
        float u0 = c[np][0] * rinv0, u1 = c[np][1] * rinv0;
        float v0 = c[np][2] * rinv1, v1 = c[np][3] * rinv1;
        u0 = u0 > 0.f ? u0 : expm1f(u0);
        u1 = u1 > 0.f ? u1 : expm1f(u1);
        v0 = v0 > 0.f ? v0 : expm1f(v0);
        v1 = v1 > 0.f ? v1 : expm1f(v1);
        *(float2*)(op0 + col) = make_float2(u0, u1);
        *(float2*)(op1 + col) = make_float2(v0, v1);
    }
}

// ---------------- 4) hout = x_cat @ W_out -----------------------------------
__global__ __launch_bounds__(256) void k_out_gemm(const float* __restrict__ Wout) {
    __shared__ float ws[512 * 16];
    __shared__ float xs[16 * 128];
    int tid = threadIdx.x;
    {
        float4* ws4 = (float4*)ws;
        const float4* wg4 = (const float4*)Wout;
        #pragma unroll
        for (int i = 0; i < 8; i++) ws4[tid + i * 256] = wg4[tid + i * 256];
    }
    int n0 = blockIdx.x * 16;
    const float4* xg4 = (const float4*)g_xcat + (size_t)n0 * 128;
    int lr = tid >> 4, c = tid & 15;
    float acc = 0.f;
    for (int kc = 0; kc < 4; kc++) {
        __syncthreads();
        float4* xs4 = (float4*)xs;
        #pragma unroll
        for (int i = 0; i < 2; i++) {
            int idx = tid + i * 256;
            int row = idx >> 5, col = idx & 31;
            xs4[idx] = xg4[row * 128 + kc * 32 + col];
        }
        __syncthreads();
        #pragma unroll 8
        for (int kk = 0; kk < 128; kk++)
            acc = fmaf(xs[lr * 128 + kk], ws[(kc * 128 + kk) * 16 + c], acc);
    }
    g_hout[(n0 + lr) * 16 + c] = acc;
}

// ---------------- 5) f1o/f2o ------------------------------------------------
__global__ void k_f12o(const float* __restrict__ a1o, const float* __restrict__ a2o) {
    int bn = blockIdx.x * 256 + threadIdx.x;
    const float* hp = g_hout + bn * 16;
    float s1 = 0.f, s2 = 0.f;
    #pragma unroll
    for (int c = 0; c < 16; c++) { s1 = fmaf(hp[c], a1o[c], s1); s2 = fmaf(hp[c], a2o[c], s2); }
    g_f1o[bn] = s1; g_f2o[bn] = s2;
}

// ---------------- 6) output attention (F=16, single-pass) -------------------
__global__ __launch_bounds__(256) void k_attn_out(float* __restrict__ out) {
    int b = blockIdx.y, n0 = blockIdx.x * 64;
    __shared__ float    f2s[NN];
    __shared__ float    f1s[64];
    __shared__ unsigned adjw[64 * 16];
    __shared__ float    hs[64 * 16];
    __shared__ float    ps[64 * 68];
    int tid = threadIdx.x;

    for (int i = tid; i < NN; i += 256) f2s[i] = g_f2o[b * NN + i];
    if (tid < 64) f1s[tid] = g_f1o[b * NN + n0 + tid];
    {
        const unsigned* ab = g_adjb + (size_t)(b * NN + n0) * 16;
        for (int i = tid; i < 1024; i += 256) adjw[i] = ab[i];
    }

    int r = tid >> 2, q = tid & 3;
    float s = 0.f;
    float4 acc = {0, 0, 0, 0};
    const float4* hg4 = (const float4*)g_hout + (size_t)b * NN * 4;
    for (int c = 0; c < 8; c++) {
        __syncthreads();
        ((float4*)hs)[tid] = hg4[c * 256 + tid];
        #pragma unroll
        for (int i = 0; i < 16; i++) {
            int idx = tid + i * 256;
            int r2 = idx >> 6, mloc = idx & 63, m2 = (c << 6) + mloc;
            float z = f1s[r2] + f2s[m2];
            float e = fmaxf(z, ALPHA * z);
            unsigned bit = (adjw[(r2 << 4) + (m2 >> 5)] >> (m2 & 31)) & 1u;
            ps[r2 * 68 + mloc] = bit ? __expf(e) : 0.f;
        }
        __syncthreads();
        #pragma unroll 8
        for (int mm = 0; mm < 64; mm++) {
            float p = ps[r * 68 + mm];
            s += p;
            float4 hv = ((const float4*)hs)[mm * 4 + q];
            acc.x = fmaf(p, hv.x, acc.x); acc.y = fmaf(p, hv.y, acc.y);
            acc.z = fmaf(p, hv.z, acc.z); acc.w = fmaf(p, hv.w, acc.w);
        }
    }
    float rinv = 1.0f / s;
    acc.x *= rinv; acc.y *= rinv; acc.z *= rinv; acc.w *= rinv;
    *(float4*)&out[(size_t)(b * NN + n0 + r) * NC + (q << 2)] = acc;
}

// ---------------- launch ----------------------------------------------------
extern "C" void kernel_launch(void* const* d_in, const int* in_sizes, int n_in,
                              void* d_out, int out_size) {
    const float* x   = (const float*)d_in[0];
    const int*   adj = (const int*)  d_in[1];
    const float* Wh  = (const float*)d_in[2];
    const float* a1h = (const float*)d_in[3];
    const float* a2h = (const float*)d_in[4];
    const float* Wo  = (const float*)d_in[5];
    const float* a1o = (const float*)d_in[6];
    const float* a2o = (const float*)d_in[7];
    float* out = (float*)d_out;

    cudaFuncSetAttribute(k_attn, cudaFuncAttributeMaxDynamicSharedMemorySize, SMEM_ATTN);

    k_pack_adj <<<BB * NN * 16 / 8, 256>>>(adj);
    k_head_gemm<<<dim3(8, BB, NH), 256>>>(x, Wh, a1h, a2h);
    k_attn     <<<dim3(4, BB, NH), 256, SMEM_ATTN>>>();
    k_out_gemm <<<BB * NN / 16, 256>>>(Wo);
    k_f12o     <<<BB * NN / 256, 256>>>(a1o, a2o);
    k_attn_out <<<dim3(8, BB), 256>>>(out);
}

// round 7
// speedup vs baseline: 4.4560x; 1.1468x over previous
#include <cuda_runtime.h>
#include <cuda_bf16.h>
#include <math.h>
#include <stdint.h>

#define BB 32
#define NN 512
#define NF 128
#define FH 64
#define NH 8
#define NC 16
#define ALPHA 0.2f

// ---------------- scratch (device globals; allocation-free rule) -------------
__device__ float          g_f1[NH*BB*NN];
__device__ float          g_f2[NH*BB*NN];
__device__ unsigned       g_adjb[BB*NN*(NN/32)];    // adjacency bitmask [B][N][16]
__device__ __nv_bfloat16  g_x_hi[BB*NN*NF];         // x split hi [B*N][128]
__device__ __nv_bfloat16  g_x_lo[BB*NN*NF];
__device__ __nv_bfloat16  g_WT_hi[NH*FH*NF];        // W^T split [H][f][k]
__device__ __nv_bfloat16  g_WT_lo[NH*FH*NF];
__device__ __nv_bfloat16  g_hT_hi[NH*BB*FH*NN];     // h^T hi [H*B][f][m]
__device__ __nv_bfloat16  g_hT_lo[NH*BB*FH*NN];     // h^T lo
__device__ float          g_houtp[NH*BB*NN*NC];     // per-head partial hout
__device__ float          g_hout[BB*NN*NC];
__device__ float          g_f1o[BB*NN];
__device__ float          g_f2o[BB*NN];

// ---------------- helpers ----------------------------------------------------
__device__ __forceinline__ uint32_t smem_u32(const void* p) {
    uint32_t a;
    asm("{ .reg .u64 t; cvta.to.shared.u64 t, %1; cvt.u32.u64 %0, t; }"
        : "=r"(a) : "l"(p));
    return a;
}
#define SWZ(o) ((o) ^ ((((unsigned)(o)) >> 3) & 0x70))

__device__ __forceinline__ unsigned packbf2(__nv_bfloat16 a, __nv_bfloat16 b) {
    __nv_bfloat162 p; p.x = a; p.y = b;
    return *(unsigned*)&p;
}
__device__ __forceinline__ void split2(float v0, float v1, unsigned& hw, unsigned& lw) {
    __nv_bfloat16 h0 = __float2bfloat16(v0), h1 = __float2bfloat16(v1);
    __nv_bfloat16 l0 = __float2bfloat16(v0 - __bfloat162float(h0));
    __nv_bfloat16 l1 = __float2bfloat16(v1 - __bfloat162float(h1));
    hw = packbf2(h0, h1);
    lw = packbf2(l0, l1);
}

#define LDSM_X4(r0, r1, r2, r3, addr) \
    asm volatile("ldmatrix.sync.aligned.m8n8.x4.shared.b16 {%0,%1,%2,%3}, [%4];" \
        : "=r"(r0), "=r"(r1), "=r"(r2), "=r"(r3) : "r"(addr))

#define MMA16816(c, a0, a1, a2, a3, b0, b1) \
    asm volatile("mma.sync.aligned.m16n8k16.row.col.f32.bf16.bf16.f32 " \
        "{%0,%1,%2,%3}, {%4,%5,%6,%7}, {%8,%9}, {%0,%1,%2,%3};" \
        : "+f"((c)[0]), "+f"((c)[1]), "+f"((c)[2]), "+f"((c)[3]) \
        : "r"(a0), "r"(a1), "r"(a2), "r"(a3), "r"(b0), "r"(b1))

// ---------------- 1) pack adjacency to bits ---------------------------------
__global__ void k_pack_adj(const int* __restrict__ adj) {
    int gw   = blockIdx.x * 8 + (threadIdx.x >> 5);
    int lane = threadIdx.x & 31;
    int m  = ((gw & 15) << 5) | lane;
    int bn = gw >> 4;
    int v  = adj[bn * NN + m] > 0;
    unsigned msk = __ballot_sync(0xffffffffu, v);
    if (lane == 0) g_adjb[gw] = msk;
}

// ---------------- 1b) split x and W^T into bf16 hi/lo -----------------------
__global__ void k_prep(const float* __restrict__ x, const float* __restrict__ W) {
    int tid = threadIdx.x;
    if (blockIdx.x < 2048) {
        int gid = blockIdx.x * 256 + tid;           // 524288 threads, 4 floats each
        float4 v = ((const float4*)x)[gid];
        unsigned h0, l0, h1, l1;
        split2(v.x, v.y, h0, l0);
        split2(v.z, v.w, h1, l1);
        ((uint2*)g_x_hi)[gid] = make_uint2(h0, h1);
        ((uint2*)g_x_lo)[gid] = make_uint2(l0, l1);
    } else {
        int gid = (blockIdx.x - 2048) * 256 + tid;  // 16384 threads, 4 elems along k
        int idx = gid * 4;                           // [h][f][k] flat
        int h = idx >> 13, rem = idx & 8191;
        int f = rem >> 7, k0 = rem & 127;
        const float* wp = W + h * NF * FH + f;       // W[h][k][f]
        float v0 = wp[(k0 + 0) * FH], v1 = wp[(k0 + 1) * FH];
        float v2 = wp[(k0 + 2) * FH], v3 = wp[(k0 + 3) * FH];
        unsigned h0, l0, h1, l1;
        split2(v0, v1, h0, l0);
        split2(v2, v3, h1, l1);
        ((uint2*)g_WT_hi)[gid] = make_uint2(h0, h1);
        ((uint2*)g_WT_lo)[gid] = make_uint2(l0, l1);
    }
}

// ---------------- 2) h = x @ W per head via HMMA bf16x3 + epilogue ----------
// Block = (n-tile 64, b, head), 128 threads = 4 warps. SMEM: x tile hi/lo
// [2][64][64] bf16 and W^T tile hi/lo, each 16KB. Epilogue computes f1/f2 and
// h^T hi/lo for the attention stage.
#define HG_XH 0
#define HG_XL 16384
#define HG_WH 32768
#define HG_WL 49152
#define SMEM_HG 65536

__global__ __launch_bounds__(128) void k_head_gemm(const float* __restrict__ a1h,
                                                   const float* __restrict__ a2h) {
    extern __shared__ char sm[];
    uint32_t smb = smem_u32(sm);
    int head = blockIdx.z, b = blockIdx.y, n0 = blockIdx.x * 64;
    int hb = head * BB + b;
    int tid = threadIdx.x, warp = tid >> 5, lane = tid & 31;

    // load tiles (layout: [khalf][row][64k], SW128 rows of 128B)
    {
        const uint4* xh4 = (const uint4*)g_x_hi + (size_t)(b * NN + n0) * 16;
        const uint4* xl4 = (const uint4*)g_x_lo + (size_t)(b * NN + n0) * 16;
        const uint4* wh4 = (const uint4*)g_WT_hi + (size_t)head * FH * 16;
        const uint4* wl4 = (const uint4*)g_WT_lo + (size_t)head * FH * 16;
        #pragma unroll
        for (int i = 0; i < 8; i++) {
            int idx = tid + i * 128;               // 0..1023
            int row = idx >> 4, kq = idx & 15;
            uint32_t off = (kq >> 3) * 8192 + SWZ(row * 128 + (kq & 7) * 16);
            *(uint4*)(sm + HG_XH + off) = xh4[idx];
            *(uint4*)(sm + HG_XL + off) = xl4[idx];
            *(uint4*)(sm + HG_WH + off) = wh4[idx];
            *(uint4*)(sm + HG_WL + off) = wl4[idx];
        }
    }
    __syncthreads();

    int q = lane >> 3, ri = lane & 7;
    int arow = warp * 16 + ((q & 1) << 3) + ri;
    int frow = ((q & 1) << 3) + ri;
    int akb  = (q >> 1) << 4;

    float c[8][4];
    #pragma unroll
    for (int i = 0; i < 8; i++)
        #pragma unroll
        for (int j = 0; j < 4; j++) c[i][j] = 0.f;

    #pragma unroll
    for (int kc = 0; kc < 8; kc++) {
        uint32_t kbase = (kc >> 2) * 8192 + (kc & 3) * 32 + akb;
        uint32_t ao = (kc >> 2) * 8192 + SWZ(arow * 128 + (kc & 3) * 32 + akb);
        uint32_t ah[4], al[4];
        LDSM_X4(ah[0], ah[1], ah[2], ah[3], smb + HG_XH + ao);
        LDSM_X4(al[0], al[1], al[2], al[3], smb + HG_XL + ao);
        #pragma unroll
        for (int np = 0; np < 4; np++) {
            uint32_t bo = (kc >> 2) * 8192 + SWZ((np * 16 + frow) * 128 + (kc & 3) * 32 + akb);
            uint32_t bh[4], bl[4];
            LDSM_X4(bh[0], bh[1], bh[2], bh[3], smb + HG_WH + bo);
            LDSM_X4(bl[0], bl[1], bl[2], bl[3], smb + HG_WL + bo);
            MMA16816(c[np*2],   ah[0], ah[1], ah[2], ah[3], bh[0], bh[2]);
            MMA16816(c[np*2],   ah[0], ah[1], ah[2], ah[3], bl[0], bl[2]);
            MMA16816(c[np*2],   al[0], al[1], al[2], al[3], bh[0], bh[2]);
            MMA16816(c[np*2+1], ah[0], ah[1], ah[2], ah[3], bh[1], bh[3]);
            MMA16816(c[np*2+1], ah[0], ah[1], ah[2], ah[3], bl[1], bl[3]);
            MMA16816(c[np*2+1], al[0], al[1], al[2], al[3], bh[1], bh[3]);
        }
    }
    (void)0;

    // stage h [64 n][65 pad] fp32 into SMEM (tiles dead)
    __syncthreads();
    float* hstage = (float*)sm;
    int g4 = lane >> 2, t4 = lane & 3;
    int row0 = warp * 16 + g4;
    #pragma unroll
    for (int np = 0; np < 8; np++) {
        int col = np * 8 + t4 * 2;
        hstage[row0 * 65 + col]       = c[np][0];
        hstage[row0 * 65 + col + 1]   = c[np][1];
        hstage[(row0+8) * 65 + col]   = c[np][2];
        hstage[(row0+8) * 65 + col+1] = c[np][3];
    }
    __syncthreads();

    // f1/f2: 2 threads per row
    {
        int r = tid >> 1, half = tid & 1;
        float s1 = 0.f, s2 = 0.f;
        #pragma unroll
        for (int k2 = 0; k2 < 32; k2++) {
            int f = half * 32 + k2;
            float v = hstage[r * 65 + f];
            s1 = fmaf(v, a1h[head * FH + f], s1);
            s2 = fmaf(v, a2h[head * FH + f], s2);
        }
        s1 += __shfl_xor_sync(0xffffffffu, s1, 1);
        s2 += __shfl_xor_sync(0xffffffffu, s2, 1);
        if (half == 0) { g_f1[hb * NN + n0 + r] = s1; g_f2[hb * NN + n0 + r] = s2; }
    }
    // h^T hi/lo: thread -> (f = tid>>1, 32 n values)
    {
        int f = tid >> 1, nh2 = tid & 1;
        unsigned hw[16], lw[16];
        #pragma unroll
        for (int k2 = 0; k2 < 16; k2++) {
            float v0 = hstage[(nh2 * 32 + 2 * k2)     * 65 + f];
            float v1 = hstage[(nh2 * 32 + 2 * k2 + 1) * 65 + f];
            split2(v0, v1, hw[k2], lw[k2]);
        }
        size_t base = ((size_t)(hb * FH + f)) * NN + n0 + nh2 * 32;
        #pragma unroll
        for (int i = 0; i < 4; i++) {
            *(uint4*)(g_hT_hi + base + i * 8) = make_uint4(hw[i*4], hw[i*4+1], hw[i*4+2], hw[i*4+3]);
            *(uint4*)(g_hT_lo + base + i * 8) = make_uint4(lw[i*4], lw[i*4+1], lw[i*4+2], lw[i*4+3]);
        }
    }
}

// ---------------- 3) tensor-core fused attention (mma.sync bf16x3) ----------
// Fused epilogue: elu(h'/s) staged in SMEM, multiplied by Wout head-slice,
// per-head partial hout written to g_houtp (summed later by k_combine).
#define P_HI_OFF  0          // [128][64] bf16 SW128 rows = 16KB
#define P_LO_OFF  16384
#define BH_OFF    32768      // h^T chunk [64 f][64 m] bf16 = 8KB
#define BL_OFF    40960
#define F2S_OFF   49152      // 512 floats
#define SROW_OFF  51200      // 128 floats
#define SMEM_ATTN 51712
#define WOUT_OFF  34048      // 64x16 fp32 = 4KB (epilogue; P/B region dead)

__global__ __launch_bounds__(256) void k_attn(const float* __restrict__ Wout) {
    extern __shared__ char sm[];
    uint32_t smb = smem_u32(sm);
    float* f2s  = (float*)(sm + F2S_OFF);
    float* srow = (float*)(sm + SROW_OFF);
    int head = blockIdx.z, b = blockIdx.y, n0 = blockIdx.x * 128;
    int hb = head * BB + b;
    int tid = threadIdx.x, warp = tid >> 5, lane = tid & 31;

    #pragma unroll
    for (int i = 0; i < 2; i++) f2s[tid + i * 256] = g_f2[hb * NN + tid + i * 256];
    int r = tid >> 1, half = tid & 1;
    float f1v = g_f1[hb * NN + n0 + r];
    const unsigned* gadj_row = g_adjb + (size_t)(b * NN + n0 + r) * 16;

    float s = 0.f;
    float c[8][4];
    #pragma unroll
    for (int i = 0; i < 8; i++)
        #pragma unroll
        for (int j = 0; j < 4; j++) c[i][j] = 0.f;

    int q = lane >> 3, ri = lane & 7;
    int arow = warp * 16 + ((q & 1) << 3) + ri;
    int frow = ((q & 1) << 3) + ri;
    int akb  = (q >> 1) << 4;

    const uint4* shp = (const uint4*)g_hT_hi + (size_t)hb * FH * (NN / 8);
    const uint4* slp = (const uint4*)g_hT_lo + (size_t)hb * FH * (NN / 8);

    for (int ch = 0; ch < 8; ch++) {
        __syncthreads();
        // ---- produce P chunk [128 rows][64 m] hi/lo (thread = row-half, 32 m) ----
        {
            unsigned word = gadj_row[ch * 2 + half];
            const float* f2c = f2s + ch * 64 + half * 32;
            #pragma unroll
            for (int g = 0; g < 4; g++) {
                unsigned hh[4], ll[4];
                #pragma unroll
                for (int jj = 0; jj < 4; jj++) {
                    float v2[2];
                    #pragma unroll
                    for (int t = 0; t < 2; t++) {
                        int kk = g * 8 + jj * 2 + t;
                        float z = f1v + f2c[kk];
                        float e = fmaxf(z, ALPHA * z);
                        float val = ((word >> kk) & 1u) ? __expf(e) : 0.f;
                        s += val;
                        v2[t] = val;
                    }
                    split2(v2[0], v2[1], hh[jj], ll[jj]);
                }
                uint32_t off = SWZ(r * 128 + half * 64 + g * 16);
                *(uint4*)(sm + P_HI_OFF + off) = make_uint4(hh[0], hh[1], hh[2], hh[3]);
                *(uint4*)(sm + P_LO_OFF + off) = make_uint4(ll[0], ll[1], ll[2], ll[3]);
            }
        }
        // ---- load h^T chunk [64 f][64 m] hi/lo ----
        #pragma unroll
        for (int i = 0; i < 2; i++) {
            int idx = tid + i * 256;
            int f = idx >> 3, jj = idx & 7;
            uint32_t off = SWZ(f * 128 + jj * 16);
            *(uint4*)(sm + BH_OFF + off) = shp[f * 64 + ch * 8 + jj];
            *(uint4*)(sm + BL_OFF + off) = slp[f * 64 + ch * 8 + jj];
        }
        __syncthreads();
        // ---- HMMA: 4 k-steps of 16, 8 n-tiles, 3 split terms ----
        #pragma unroll
        for (int kc = 0; kc < 4; kc++) {
            uint32_t ao = SWZ(arow * 128 + kc * 32 + akb);
            uint32_t ah[4], al[4];
            LDSM_X4(ah[0], ah[1], ah[2], ah[3], smb + P_HI_OFF + ao);
            LDSM_X4(al[0], al[1], al[2], al[3], smb + P_LO_OFF + ao);
            #pragma unroll
            for (int np = 0; np < 4; np++) {
                uint32_t bo = SWZ((np * 16 + frow) * 128 + kc * 32 + akb);
                uint32_t bh[4], bl[4];
                LDSM_X4(bh[0], bh[1], bh[2], bh[3], smb + BH_OFF + bo);
                LDSM_X4(bl[0], bl[1], bl[2], bl[3], smb + BL_OFF + bo);
                MMA16816(c[np*2],   ah[0], ah[1], ah[2], ah[3], bh[0], bh[2]);
                MMA16816(c[np*2],   ah[0], ah[1], ah[2], ah[3], bl[0], bl[2]);
                MMA16816(c[np*2],   al[0], al[1], al[2], al[3], bh[0], bh[2]);
                MMA16816(c[np*2+1], ah[0], ah[1], ah[2], ah[3], bh[1], bh[3]);
                MMA16816(c[np*2+1], ah[0], ah[1], ah[2], ah[3], bl[1], bl[3]);
                MMA16816(c[np*2+1], al[0], al[1], al[2], al[3], bh[1], bh[3]);
            }
        }
    }

    // ---- row sums -> SMEM ----
    s += __shfl_xor_sync(0xffffffffu, s, 1);
    if (half == 0) srow[r] = s;
    __syncthreads();

    // ---- stage elu(h'/s) [128][65] fp32 + load Wout slice ----
    float* hstage = (float*)sm;
    float* swout  = (float*)(sm + WOUT_OFF);
    int g4 = lane >> 2, t4 = lane & 3;
    int row0 = warp * 16 + g4;
    float rinv0 = 1.0f / srow[row0];
    float rinv1 = 1.0f / srow[row0 + 8];
    __syncthreads();                       // srow read before overwrite region? (srow high, safe) tiles dead
    ((float4*)swout)[tid] = ((const float4*)Wout)[head * 256 + tid];
    #pragma unroll
    for (int np = 0; np < 8; np++) {
        int col = np * 8 + t4 * 2;
        float u0 = c[np][0] * rinv0, u1 = c[np][1] * rinv0;
        float v0 = c[np][2] * rinv1, v1 = c[np][3] * rinv1;
        u0 = u0 > 0.f ? u0 : expm1f(u0);
        u1 = u1 > 0.f ? u1 : expm1f(u1);
        v0 = v0 > 0.f ? v0 : expm1f(v0);
        v1 = v1 > 0.f ? v1 : expm1f(v1);
        hstage[row0 * 65 + col]         = u0;
        hstage[row0 * 65 + col + 1]     = u1;
        hstage[(row0 + 8) * 65 + col]   = v0;
        hstage[(row0 + 8) * 65 + col+1] = v1;
    }
    __syncthreads();

    // ---- partial hout: [128 rows] x [64 k] x [16 cols], thread = (row, 8 cols) ----
    {
        int row = tid >> 1, chf = tid & 1;
        float acc[8] = {};
        #pragma unroll 8
        for (int k = 0; k < 64; k++) {
            float a = hstage[row * 65 + k];
            const float* wr = swout + k * 16 + chf * 8;
            #pragma unroll
            for (int j = 0; j < 8; j++) acc[j] = fmaf(a, wr[j], acc[j]);
        }
        float* op = g_houtp + ((size_t)head * BB * NN + b * NN + n0 + row) * NC + chf * 8;
        *(float4*)op       = make_float4(acc[0], acc[1], acc[2], acc[3]);
        *(float4*)(op + 4) = make_float4(acc[4], acc[5], acc[6], acc[7]);
    }
}

// ---------------- 4) combine partial hout + f1o/f2o -------------------------
__global__ __launch_bounds__(256) void k_combine(const float* __restrict__ a1o,
                                                 const float* __restrict__ a2o) {
    int bn = blockIdx.x * 256 + threadIdx.x;
    float acc[16] = {};
    #pragma unroll
    for (int h = 0; h < NH; h++) {
        const float4* p = (const float4*)(g_houtp + ((size_t)h * BB * NN + bn) * NC);
        #pragma unroll
        for (int i = 0; i < 4; i++) {
            float4 v = p[i];
            acc[i*4]   += v.x; acc[i*4+1] += v.y;
            acc[i*4+2] += v.z; acc[i*4+3] += v.w;
        }
    }
    float4* op = (float4*)(g_hout + (size_t)bn * NC);
    #pragma unroll
    for (int i = 0; i < 4; i++)
        op[i] = make_float4(acc[i*4], acc[i*4+1], acc[i*4+2], acc[i*4+3]);
    float s1 = 0.f, s2 = 0.f;
    #pragma unroll
    for (int c = 0; c < 16; c++) { s1 = fmaf(acc[c], a1o[c], s1); s2 = fmaf(acc[c], a2o[c], s2); }
    g_f1o[bn] = s1; g_f2o[bn] = s2;
}

// ---------------- 5) output attention (F=16, single-pass) -------------------
__global__ __launch_bounds__(256) void k_attn_out(float* __restrict__ out) {
    int b = blockIdx.y, n0 = blockIdx.x * 64;
    __shared__ float    f2s[NN];
    __shared__ float    f1s[64];
    __shared__ unsigned adjw[64 * 16];
    __shared__ float    hs[64 * 16];
    __shared__ float    ps[64 * 68];
    int tid = threadIdx.x;

    for (int i = tid; i < NN; i += 256) f2s[i] = g_f2o[b * NN + i];
    if (tid < 64) f1s[tid] = g_f1o[b * NN + n0 + tid];
    {
        const unsigned* ab = g_adjb + (size_t)(b * NN + n0) * 16;
        for (int i = tid; i < 1024; i += 256) adjw[i] = ab[i];
    }

    int r = tid >> 2, q = tid & 3;
    float s = 0.f;
    float4 acc = {0, 0, 0, 0};
    const float4* hg4 = (const float4*)g_hout + (size_t)b * NN * 4;
    for (int c = 0; c < 8; c++) {
        __syncthreads();
        ((float4*)hs)[tid] = hg4[c * 256 + tid];
        #pragma unroll
        for (int i = 0; i < 16; i++) {
            int idx = tid + i * 256;
            int r2 = idx >> 6, mloc = idx & 63, m2 = (c << 6) + mloc;
            float z = f1s[r2] + f2s[m2];
            float e = fmaxf(z, ALPHA * z);
            unsigned bit = (adjw[(r2 << 4) + (m2 >> 5)] >> (m2 & 31)) & 1u;
            ps[r2 * 68 + mloc] = bit ? __expf(e) : 0.f;
        }
        __syncthreads();
        #pragma unroll 8
        for (int mm = 0; mm < 64; mm++) {
            float p = ps[r * 68 + mm];
            s += p;
            float4 hv = ((const float4*)hs)[mm * 4 + q];
            acc.x = fmaf(p, hv.x, acc.x); acc.y = fmaf(p, hv.y, acc.y);
            acc.z = fmaf(p, hv.z, acc.z); acc.w = fmaf(p, hv.w, acc.w);
        }
    }
    float rinv = 1.0f / s;
    acc.x *= rinv; acc.y *= rinv; acc.z *= rinv; acc.w *= rinv;
    *(float4*)&out[(size_t)(b * NN + n0 + r) * NC + (q << 2)] = acc;
}

// ---------------- launch ----------------------------------------------------
extern "C" void kernel_launch(void* const* d_in, const int* in_sizes, int n_in,
                              void* d_out, int out_size) {
    const float* x   = (const float*)d_in[0];
    const int*   adj = (const int*)  d_in[1];
    const float* Wh  = (const float*)d_in[2];
    const float* a1h = (const float*)d_in[3];
    const float* a2h = (const float*)d_in[4];
    const float* Wo  = (const float*)d_in[5];
    const float* a1o = (const float*)d_in[6];
    const float* a2o = (const float*)d_in[7];
    float* out = (float*)d_out;

    cudaFuncSetAttribute(k_head_gemm, cudaFuncAttributeMaxDynamicSharedMemorySize, SMEM_HG);
    cudaFuncSetAttribute(k_attn, cudaFuncAttributeMaxDynamicSharedMemorySize, SMEM_ATTN);

    k_pack_adj <<<BB * NN * 16 / 8, 256>>>(adj);
    k_prep     <<<2112, 256>>>(x, Wh);
    k_head_gemm<<<dim3(8, BB, NH), 128, SMEM_HG>>>(a1h, a2h);
    k_attn     <<<dim3(4, BB, NH), 256, SMEM_ATTN>>>(Wo);
    k_combine  <<<BB * NN / 256, 256>>>(a1o, a2o);
    k_attn_out <<<dim3(8, BB), 256>>>(out);
}

// round 8
// speedup vs baseline: 5.2854x; 1.1861x over previous
#include <cuda_runtime.h>
#include <cuda_bf16.h>
#include <math.h>
#include <stdint.h>

#define BB 32
#define NN 512
#define NF 128
#define FH 64
#define NH 8
#define NC 16
#define ALPHA 0.2f

// ---------------- scratch (device globals; allocation-free rule) -------------
__device__ float          g_f1[NH*BB*NN];
__device__ float          g_f2[NH*BB*NN];
__device__ unsigned       g_adjb[BB*NN*(NN/32)];    // adjacency bitmask [B][N][16]
__device__ __nv_bfloat16  g_x_hi[BB*NN*NF];         // x split hi [B*N][128]
__device__ __nv_bfloat16  g_x_lo[BB*NN*NF];
__device__ __nv_bfloat16  g_WT_hi[NH*FH*NF];        // W^T split [H][f][k]
__device__ __nv_bfloat16  g_WT_lo[NH*FH*NF];
__device__ __nv_bfloat16  g_hT_hi[NH*BB*FH*NN];     // h^T hi [H*B][f][m]
__device__ __nv_bfloat16  g_hT_lo[NH*BB*FH*NN];     // h^T lo
__device__ float          g_houtp[NH*BB*NN*NC];     // per-head partial hout
__device__ float          g_hout[BB*NN*NC];
__device__ float          g_f1o[BB*NN];
__device__ float          g_f2o[BB*NN];

// ---------------- helpers ----------------------------------------------------
__device__ __forceinline__ uint32_t smem_u32(const void* p) {
    uint32_t a;
    asm("{ .reg .u64 t; cvta.to.shared.u64 t, %1; cvt.u32.u64 %0, t; }"
        : "=r"(a) : "l"(p));
    return a;
}
#define SWZ(o) ((o) ^ ((((unsigned)(o)) >> 3) & 0x70))

__device__ __forceinline__ unsigned packbf2(__nv_bfloat16 a, __nv_bfloat16 b) {
    __nv_bfloat162 p; p.x = a; p.y = b;
    return *(unsigned*)&p;
}
__device__ __forceinline__ void split2(float v0, float v1, unsigned& hw, unsigned& lw) {
    __nv_bfloat16 h0 = __float2bfloat16(v0), h1 = __float2bfloat16(v1);
    __nv_bfloat16 l0 = __float2bfloat16(v0 - __bfloat162float(h0));
    __nv_bfloat16 l1 = __float2bfloat16(v1 - __bfloat162float(h1));
    hw = packbf2(h0, h1);
    lw = packbf2(l0, l1);
}
// truncation split: hi = top-16 bits (exact via PRMT), lo = v - hi (rn bf16x2)
__device__ __forceinline__ void split2t(float v0, float v1, unsigned& hw, unsigned& lw) {
    unsigned b0 = __float_as_uint(v0), b1 = __float_as_uint(v1);
    hw = __byte_perm(b0, b1, 0x7632);
    float l0 = v0 - __uint_as_float(b0 & 0xffff0000u);
    float l1 = v1 - __uint_as_float(b1 & 0xffff0000u);
    asm("cvt.rn.bf16x2.f32 %0, %1, %2;" : "=r"(lw) : "f"(l1), "f"(l0));
}

#define LDSM_X4(r0, r1, r2, r3, addr) \
    asm volatile("ldmatrix.sync.aligned.m8n8.x4.shared.b16 {%0,%1,%2,%3}, [%4];" \
        : "=r"(r0), "=r"(r1), "=r"(r2), "=r"(r3) : "r"(addr))

#define MMA16816(c, a0, a1, a2, a3, b0, b1) \
    asm volatile("mma.sync.aligned.m16n8k16.row.col.f32.bf16.bf16.f32 " \
        "{%0,%1,%2,%3}, {%4,%5,%6,%7}, {%8,%9}, {%0,%1,%2,%3};" \
        : "+f"((c)[0]), "+f"((c)[1]), "+f"((c)[2]), "+f"((c)[3]) \
        : "r"(a0), "r"(a1), "r"(a2), "r"(a3), "r"(b0), "r"(b1))

// ---------------- 1) pack adjacency to bits ---------------------------------
__global__ void k_pack_adj(const int* __restrict__ adj) {
    int gw   = blockIdx.x * 8 + (threadIdx.x >> 5);
    int lane = threadIdx.x & 31;
    int m  = ((gw & 15) << 5) | lane;
    int bn = gw >> 4;
    int v  = adj[bn * NN + m] > 0;
    unsigned msk = __ballot_sync(0xffffffffu, v);
    if (lane == 0) g_adjb[gw] = msk;
}

// ---------------- 1b) split x and W^T into bf16 hi/lo -----------------------
__global__ void k_prep(const float* __restrict__ x, const float* __restrict__ W) {
    int tid = threadIdx.x;
    if (blockIdx.x < 2048) {
        int gid = blockIdx.x * 256 + tid;
        float4 v = ((const float4*)x)[gid];
        unsigned h0, l0, h1, l1;
        split2(v.x, v.y, h0, l0);
        split2(v.z, v.w, h1, l1);
        ((uint2*)g_x_hi)[gid] = make_uint2(h0, h1);
        ((uint2*)g_x_lo)[gid] = make_uint2(l0, l1);
    } else {
        int gid = (blockIdx.x - 2048) * 256 + tid;
        int idx = gid * 4;
        int h = idx >> 13, rem = idx & 8191;
        int f = rem >> 7, k0 = rem & 127;
        const float* wp = W + h * NF * FH + f;
        float v0 = wp[(k0 + 0) * FH], v1 = wp[(k0 + 1) * FH];
        float v2 = wp[(k0 + 2) * FH], v3 = wp[(k0 + 3) * FH];
        unsigned h0, l0, h1, l1;
        split2(v0, v1, h0, l0);
        split2(v2, v3, h1, l1);
        ((uint2*)g_WT_hi)[gid] = make_uint2(h0, h1);
        ((uint2*)g_WT_lo)[gid] = make_uint2(l0, l1);
    }
}

// ---------------- 2) h = x @ W per head via HMMA bf16x3 + epilogue ----------
#define HG_XH 0
#define HG_XL 16384
#define HG_WH 32768
#define HG_WL 49152
#define SMEM_HG 65536

__global__ __launch_bounds__(128) void k_head_gemm(const float* __restrict__ a1h,
                                                   const float* __restrict__ a2h) {
    extern __shared__ char sm[];
    uint32_t smb = smem_u32(sm);
    int head = blockIdx.z, b = blockIdx.y, n0 = blockIdx.x * 64;
    int hb = head * BB + b;
    int tid = threadIdx.x, warp = tid >> 5, lane = tid & 31;

    {
        const uint4* xh4 = (const uint4*)g_x_hi + (size_t)(b * NN + n0) * 16;
        const uint4* xl4 = (const uint4*)g_x_lo + (size_t)(b * NN + n0) * 16;
        const uint4* wh4 = (const uint4*)g_WT_hi + (size_t)head * FH * 16;
        const uint4* wl4 = (const uint4*)g_WT_lo + (size_t)head * FH * 16;
        #pragma unroll
        for (int i = 0; i < 8; i++) {
            int idx = tid + i * 128;
            int row = idx >> 4, kq = idx & 15;
            uint32_t off = (kq >> 3) * 8192 + SWZ(row * 128 + (kq & 7) * 16);
            *(uint4*)(sm + HG_XH + off) = xh4[idx];
            *(uint4*)(sm + HG_XL + off) = xl4[idx];
            *(uint4*)(sm + HG_WH + off) = wh4[idx];
            *(uint4*)(sm + HG_WL + off) = wl4[idx];
        }
    }
    __syncthreads();

    int q = lane >> 3, ri = lane & 7;
    int arow = warp * 16 + ((q & 1) << 3) + ri;
    int frow = ((q & 1) << 3) + ri;
    int akb  = (q >> 1) << 4;

    float c[8][4];
    #pragma unroll
    for (int i = 0; i < 8; i++)
        #pragma unroll
        for (int j = 0; j < 4; j++) c[i][j] = 0.f;

    #pragma unroll
    for (int kc = 0; kc < 8; kc++) {
        uint32_t ao = (kc >> 2) * 8192 + SWZ(arow * 128 + (kc & 3) * 32 + akb);
        uint32_t ah[4], al[4];
        LDSM_X4(ah[0], ah[1], ah[2], ah[3], smb + HG_XH + ao);
        LDSM_X4(al[0], al[1], al[2], al[3], smb + HG_XL + ao);
        #pragma unroll
        for (int np = 0; np < 4; np++) {
            uint32_t bo = (kc >> 2) * 8192 + SWZ((np * 16 + frow) * 128 + (kc & 3) * 32 + akb);
            uint32_t bh[4], bl[4];
            LDSM_X4(bh[0], bh[1], bh[2], bh[3], smb + HG_WH + bo);
            LDSM_X4(bl[0], bl[1], bl[2], bl[3], smb + HG_WL + bo);
            MMA16816(c[np*2],   ah[0], ah[1], ah[2], ah[3], bh[0], bh[2]);
            MMA16816(c[np*2],   ah[0], ah[1], ah[2], ah[3], bl[0], bl[2]);
            MMA16816(c[np*2],   al[0], al[1], al[2], al[3], bh[0], bh[2]);
            MMA16816(c[np*2+1], ah[0], ah[1], ah[2], ah[3], bh[1], bh[3]);
            MMA16816(c[np*2+1], ah[0], ah[1], ah[2], ah[3], bl[1], bl[3]);
            MMA16816(c[np*2+1], al[0], al[1], al[2], al[3], bh[1], bh[3]);
        }
    }

    __syncthreads();
    float* hstage = (float*)sm;
    int g4 = lane >> 2, t4 = lane & 3;
    int row0 = warp * 16 + g4;
    #pragma unroll
    for (int np = 0; np < 8; np++) {
        int col = np * 8 + t4 * 2;
        hstage[row0 * 65 + col]       = c[np][0];
        hstage[row0 * 65 + col + 1]   = c[np][1];
        hstage[(row0+8) * 65 + col]   = c[np][2];
        hstage[(row0+8) * 65 + col+1] = c[np][3];
    }
    __syncthreads();

    {
        int r = tid >> 1, half = tid & 1;
        float s1 = 0.f, s2 = 0.f;
        #pragma unroll
        for (int k2 = 0; k2 < 32; k2++) {
            int f = half * 32 + k2;
            float v = hstage[r * 65 + f];
            s1 = fmaf(v, a1h[head * FH + f], s1);
            s2 = fmaf(v, a2h[head * FH + f], s2);
        }
        s1 += __shfl_xor_sync(0xffffffffu, s1, 1);
        s2 += __shfl_xor_sync(0xffffffffu, s2, 1);
        if (half == 0) { g_f1[hb * NN + n0 + r] = s1; g_f2[hb * NN + n0 + r] = s2; }
    }
    {
        int f = tid >> 1, nh2 = tid & 1;
        unsigned hw[16], lw[16];
        #pragma unroll
        for (int k2 = 0; k2 < 16; k2++) {
            float v0 = hstage[(nh2 * 32 + 2 * k2)     * 65 + f];
            float v1 = hstage[(nh2 * 32 + 2 * k2 + 1) * 65 + f];
            split2(v0, v1, hw[k2], lw[k2]);
        }
        size_t base = ((size_t)(hb * FH + f)) * NN + n0 + nh2 * 32;
        #pragma unroll
        for (int i = 0; i < 4; i++) {
            *(uint4*)(g_hT_hi + base + i * 8) = make_uint4(hw[i*4], hw[i*4+1], hw[i*4+2], hw[i*4+3]);
            *(uint4*)(g_hT_lo + base + i * 8) = make_uint4(lw[i*4], lw[i*4+1], lw[i*4+2], lw[i*4+3]);
        }
    }
}

// ---------------- 3) tensor-core fused attention (mma.sync bf16x3) ----------
// Factorized exp: exp(leaky(f1+f2)) = (z>0 ? e^f1 e^f2 : e^.2f1 e^.2f2);
// sign test via e^f2 > e^-f1 (monotone). Truncation-based bf16 split for P.
#define P_HI_OFF  0          // [128][64] bf16 SW128 rows = 16KB
#define P_LO_OFF  16384
#define BH_OFF    32768      // h^T chunk [64 f][64 m] bf16 = 8KB
#define BL_OFF    40960
#define F2P_OFF   49152      // 512 float2 = 4KB
#define SROW_OFF  53248      // 128 floats
#define SMEM_ATTN 53760
#define WOUT_OFF  34048      // 64x16 fp32 (epilogue; P/B region dead)

__global__ __launch_bounds__(256) void k_attn(const float* __restrict__ Wout) {
    extern __shared__ char sm[];
    uint32_t smb = smem_u32(sm);
    float2* f2p = (float2*)(sm + F2P_OFF);
    float* srow = (float*)(sm + SROW_OFF);
    int head = blockIdx.z, b = blockIdx.y, n0 = blockIdx.x * 128;
    int hb = head * BB + b;
    int tid = threadIdx.x, warp = tid >> 5, lane = tid & 31;

    // factorized-exp tables
    #pragma unroll
    for (int i = 0; i < 2; i++) {
        int m = tid + i * 256;
        float f2v = g_f2[hb * NN + m];
        f2p[m] = make_float2(__expf(f2v), __expf(ALPHA * f2v));
    }
    int r = tid >> 1, half = tid & 1;
    float f1v = g_f1[hb * NN + n0 + r];
    float Ae = __expf(f1v), A2e = __expf(ALPHA * f1v), Ce = __expf(-f1v);
    const unsigned* gadj_row = g_adjb + (size_t)(b * NN + n0 + r) * 16;

    float s = 0.f;
    float c[8][4];
    #pragma unroll
    for (int i = 0; i < 8; i++)
        #pragma unroll
        for (int j = 0; j < 4; j++) c[i][j] = 0.f;

    int q = lane >> 3, ri = lane & 7;
    int arow = warp * 16 + ((q & 1) << 3) + ri;
    int frow = ((q & 1) << 3) + ri;
    int akb  = (q >> 1) << 4;

    const uint4* shp = (const uint4*)g_hT_hi + (size_t)hb * FH * (NN / 8);
    const uint4* slp = (const uint4*)g_hT_lo + (size_t)hb * FH * (NN / 8);

    for (int ch = 0; ch < 8; ch++) {
        __syncthreads();
        // ---- produce P chunk [128 rows][64 m] hi/lo ----
        {
            unsigned word = gadj_row[ch * 2 + half];
            const float2* bp = f2p + ch * 64 + half * 32;
            #pragma unroll
            for (int g = 0; g < 4; g++) {
                unsigned hh[4], ll[4];
                #pragma unroll
                for (int pj = 0; pj < 4; pj++) {
                    float vv[2];
                    #pragma unroll
                    for (int t = 0; t < 2; t++) {
                        int kk = g * 8 + pj * 2 + t;
                        float2 Bv = bp[kk];
                        bool pos = Bv.x > Ce;
                        float val = (pos ? Ae : A2e) * (pos ? Bv.x : Bv.y);
                        val = ((word >> kk) & 1u) ? val : 0.f;
                        s += val;
                        vv[t] = val;
                    }
                    split2t(vv[0], vv[1], hh[pj], ll[pj]);
                }
                uint32_t off = SWZ(r * 128 + half * 64 + g * 16);
                *(uint4*)(sm + P_HI_OFF + off) = make_uint4(hh[0], hh[1], hh[2], hh[3]);
                *(uint4*)(sm + P_LO_OFF + off) = make_uint4(ll[0], ll[1], ll[2], ll[3]);
            }
        }
        // ---- load h^T chunk [64 f][64 m] hi/lo ----
        #pragma unroll
        for (int i = 0; i < 2; i++) {
            int idx = tid + i * 256;
            int f = idx >> 3, jj = idx & 7;
            uint32_t off = SWZ(f * 128 + jj * 16);
            *(uint4*)(sm + BH_OFF + off) = shp[f * 64 + ch * 8 + jj];
            *(uint4*)(sm + BL_OFF + off) = slp[f * 64 + ch * 8 + jj];
        }
        __syncthreads();
        // ---- HMMA: 4 k-steps of 16, 8 n-tiles, 3 split terms ----
        #pragma unroll
        for (int kc = 0; kc < 4; kc++) {
            uint32_t ao = SWZ(arow * 128 + kc * 32 + akb);
            uint32_t ah[4], al[4];
            LDSM_X4(ah[0], ah[1], ah[2], ah[3], smb + P_HI_OFF + ao);
            LDSM_X4(al[0], al[1], al[2], al[3], smb + P_LO_OFF + ao);
            #pragma unroll
            for (int np = 0; np < 4; np++) {
                uint32_t bo = SWZ((np * 16 + frow) * 128 + kc * 32 + akb);
                uint32_t bh[4], bl[4];
                LDSM_X4(bh[0], bh[1], bh[2], bh[3], smb + BH_OFF + bo);
                LDSM_X4(bl[0], bl[1], bl[2], bl[3], smb + BL_OFF + bo);
                MMA16816(c[np*2],   ah[0], ah[1], ah[2], ah[3], bh[0], bh[2]);
                MMA16816(c[np*2],   ah[0], ah[1], ah[2], ah[3], bl[0], bl[2]);
                MMA16816(c[np*2],   al[0], al[1], al[2], al[3], bh[0], bh[2]);
                MMA16816(c[np*2+1], ah[0], ah[1], ah[2], ah[3], bh[1], bh[3]);
                MMA16816(c[np*2+1], ah[0], ah[1], ah[2], ah[3], bl[1], bl[3]);
                MMA16816(c[np*2+1], al[0], al[1], al[2], al[3], bh[1], bh[3]);
            }
        }
    }

    // ---- row sums -> SMEM ----
    s += __shfl_xor_sync(0xffffffffu, s, 1);
    if (half == 0) srow[r] = s;
    __syncthreads();

    // ---- stage elu(h'/s) [128][65] fp32 + load Wout slice ----
    float* hstage = (float*)sm;
    float* swout  = (float*)(sm + WOUT_OFF);
    int g4 = lane >> 2, t4 = lane & 3;
    int row0 = warp * 16 + g4;
    float rinv0 = 1.0f / srow[row0];
    float rinv1 = 1.0f / srow[row0 + 8];
    __syncthreads();
    ((float4*)swout)[tid] = ((const float4*)Wout)[head * 256 + tid];
    #pragma unroll
    for (int np = 0; np < 8; np++) {
        int col = np * 8 + t4 * 2;
        float u0 = c[np][0] * rinv0, u1 = c[np][1] * rinv0;
        float v0 = c[np][2] * rinv1, v1 = c[np][3] * rinv1;
        u0 = u0 > 0.f ? u0 : expm1f(u0);
        u1 = u1 > 0.f ? u1 : expm1f(u1);
        v0 = v0 > 0.f ? v0 : expm1f(v0);
        v1 = v1 > 0.f ? v1 : expm1f(v1);
        hstage[row0 * 65 + col]         = u0;
        hstage[row0 * 65 + col + 1]     = u1;
        hstage[(row0 + 8) * 65 + col]   = v0;
        hstage[(row0 + 8) * 65 + col+1] = v1;
    }
    __syncthreads();

    // ---- partial hout ----
    {
        int row = tid >> 1, chf = tid & 1;
        float acc[8] = {};
        #pragma unroll 8
        for (int k = 0; k < 64; k++) {
            float a = hstage[row * 65 + k];
            const float* wr = swout + k * 16 + chf * 8;
            #pragma unroll
            for (int j = 0; j < 8; j++) acc[j] = fmaf(a, wr[j], acc[j]);
        }
        float* op = g_houtp + ((size_t)head * BB * NN + b * NN + n0 + row) * NC + chf * 8;
        *(float4*)op       = make_float4(acc[0], acc[1], acc[2], acc[3]);
        *(float4*)(op + 4) = make_float4(acc[4], acc[5], acc[6], acc[7]);
    }
}

// ---------------- 4) combine partial hout + f1o/f2o -------------------------
__global__ __launch_bounds__(256) void k_combine(const float* __restrict__ a1o,
                                                 const float* __restrict__ a2o) {
    int bn = blockIdx.x * 256 + threadIdx.x;
    float acc[16] = {};
    #pragma unroll
    for (int h = 0; h < NH; h++) {
        const float4* p = (const float4*)(g_houtp + ((size_t)h * BB * NN + bn) * NC);
        #pragma unroll
        for (int i = 0; i < 4; i++) {
            float4 v = p[i];
            acc[i*4]   += v.x; acc[i*4+1] += v.y;
            acc[i*4+2] += v.z; acc[i*4+3] += v.w;
        }
    }
    float4* op = (float4*)(g_hout + (size_t)bn * NC);
    #pragma unroll
    for (int i = 0; i < 4; i++)
        op[i] = make_float4(acc[i*4], acc[i*4+1], acc[i*4+2], acc[i*4+3]);
    float s1 = 0.f, s2 = 0.f;
    #pragma unroll
    for (int c = 0; c < 16; c++) { s1 = fmaf(acc[c], a1o[c], s1); s2 = fmaf(acc[c], a2o[c], s2); }
    g_f1o[bn] = s1; g_f2o[bn] = s2;
}

// ---------------- 5) output attention (F=16, factorized exp) ----------------
__global__ __launch_bounds__(256) void k_attn_out(float* __restrict__ out) {
    int b = blockIdx.y, n0 = blockIdx.x * 64;
    __shared__ float2   f2p[NN];        // 4KB
    __shared__ unsigned adjw[64 * 16];  // 4KB
    __shared__ float    hs[64 * 16];    // 4KB
    __shared__ float    ps[64 * 68];    // 17.4KB
    int tid = threadIdx.x;

    #pragma unroll
    for (int i = 0; i < 2; i++) {
        int m = tid + i * 256;
        float f2v = g_f2o[b * NN + m];
        f2p[m] = make_float2(__expf(f2v), __expf(ALPHA * f2v));
    }
    {
        const unsigned* ab = g_adjb + (size_t)(b * NN + n0) * 16;
        for (int i = tid; i < 1024; i += 256) adjw[i] = ab[i];
    }
    int r = tid >> 2, q = tid & 3;
    float f1v = g_f1o[b * NN + n0 + r];
    float Ae = __expf(f1v), A2e = __expf(ALPHA * f1v), Ce = __expf(-f1v);

    float s = 0.f;
    float4 acc = {0, 0, 0, 0};
    const float4* hg4 = (const float4*)g_hout + (size_t)b * NN * 4;
    for (int c = 0; c < 8; c++) {
        __syncthreads();
        ((float4*)hs)[tid] = hg4[c * 256 + tid];
        {
            unsigned word = adjw[(r << 4) + c * 2 + (q >> 1)];
            int sb = (q & 1) * 16;
            const float2* bp = f2p + c * 64 + q * 16;
            #pragma unroll
            for (int t = 0; t < 16; t++) {
                float2 Bv = bp[t];
                bool pos = Bv.x > Ce;
                float val = (pos ? Ae : A2e) * (pos ? Bv.x : Bv.y);
                val = ((word >> (sb + t)) & 1u) ? val : 0.f;
                ps[r * 68 + q * 16 + t] = val;
            }
        }
        __syncthreads();
        #pragma unroll 8
        for (int mm = 0; mm < 64; mm++) {
            float p = ps[r * 68 + mm];
            s += p;
            float4 hv = ((const float4*)hs)[mm * 4 + q];
            acc.x = fmaf(p, hv.x, acc.x); acc.y = fmaf(p, hv.y, acc.y);
            acc.z = fmaf(p, hv.z, acc.z); acc.w = fmaf(p, hv.w, acc.w);
        }
    }
    float rinv = 1.0f / s;
    acc.x *= rinv; acc.y *= rinv; acc.z *= rinv; acc.w *= rinv;
    *(float4*)&out[(size_t)(b * NN + n0 + r) * NC + (q << 2)] = acc;
}

// ---------------- launch ----------------------------------------------------
extern "C" void kernel_launch(void* const* d_in, const int* in_sizes, int n_in,
                              void* d_out, int out_size) {
    const float* x   = (const float*)d_in[0];
    const int*   adj = (const int*)  d_in[1];
    const float* Wh  = (const float*)d_in[2];
    const float* a1h = (const float*)d_in[3];
    const float* a2h = (const float*)d_in[4];
    const float* Wo  = (const float*)d_in[5];
    const float* a1o = (const float*)d_in[6];
    const float* a2o = (const float*)d_in[7];
    float* out = (float*)d_out;

    cudaFuncSetAttribute(k_head_gemm, cudaFuncAttributeMaxDynamicSharedMemorySize, SMEM_HG);
    cudaFuncSetAttribute(k_attn, cudaFuncAttributeMaxDynamicSharedMemorySize, SMEM_ATTN);

    k_pack_adj <<<BB * NN * 16 / 8, 256>>>(adj);
    k_prep     <<<2112, 256>>>(x, Wh);
    k_head_gemm<<<dim3(8, BB, NH), 128, SMEM_HG>>>(a1h, a2h);
    k_attn     <<<dim3(4, BB, NH), 256, SMEM_ATTN>>>(Wo);
    k_combine  <<<BB * NN / 256, 256>>>(a1o, a2o);
    k_attn_out <<<dim3(8, BB), 256>>>(out);
}

// round 9
// speedup vs baseline: 5.4035x; 1.0224x over previous
#include <cuda_runtime.h>
#include <cuda_bf16.h>
#include <math.h>
#include <stdint.h>

#define BB 32
#define NN 512
#define NF 128
#define FH 64
#define NH 8
#define NC 16
#define ALPHA 0.2f

// ---------------- scratch (device globals; allocation-free rule) -------------
__device__ float          g_f1[NH*BB*NN];
__device__ float          g_f2[NH*BB*NN];
__device__ unsigned       g_adjb[BB*NN*(NN/32)];    // adjacency bitmask [B][N][16]
__device__ __nv_bfloat16  g_x_hi[BB*NN*NF];         // x split hi [B*N][128]
__device__ __nv_bfloat16  g_x_lo[BB*NN*NF];
__device__ __nv_bfloat16  g_WT_hi[NH*FH*NF];        // W^T split [H][f][k]
__device__ __nv_bfloat16  g_WT_lo[NH*FH*NF];
__device__ __nv_bfloat16  g_hT_hi[NH*BB*FH*NN];     // h^T hi [H*B][f][m]
__device__ __nv_bfloat16  g_hT_lo[NH*BB*FH*NN];     // h^T lo
__device__ float          g_houtp[NH*BB*NN*NC];     // per-head partial hout
__device__ float          g_hout[BB*NN*NC];
__device__ float          g_f1o[BB*NN];
__device__ float          g_f2o[BB*NN];

// ---------------- helpers ----------------------------------------------------
__device__ __forceinline__ uint32_t smem_u32(const void* p) {
    uint32_t a;
    asm("{ .reg .u64 t; cvta.to.shared.u64 t, %1; cvt.u32.u64 %0, t; }"
        : "=r"(a) : "l"(p));
    return a;
}
#define SWZ(o) ((o) ^ ((((unsigned)(o)) >> 3) & 0x70))
#define ONES2 0x3F803F80u   // bf16x2 {1.0, 1.0}

__device__ __forceinline__ unsigned packbf2(__nv_bfloat16 a, __nv_bfloat16 b) {
    __nv_bfloat162 p; p.x = a; p.y = b;
    return *(unsigned*)&p;
}
__device__ __forceinline__ void split2(float v0, float v1, unsigned& hw, unsigned& lw) {
    __nv_bfloat16 h0 = __float2bfloat16(v0), h1 = __float2bfloat16(v1);
    __nv_bfloat16 l0 = __float2bfloat16(v0 - __bfloat162float(h0));
    __nv_bfloat16 l1 = __float2bfloat16(v1 - __bfloat162float(h1));
    hw = packbf2(h0, h1);
    lw = packbf2(l0, l1);
}
// truncation split: hi = top-16 bits (exact via PRMT), lo = v - hi (rn bf16x2)
__device__ __forceinline__ void split2t(float v0, float v1, unsigned& hw, unsigned& lw) {
    unsigned b0 = __float_as_uint(v0), b1 = __float_as_uint(v1);
    hw = __byte_perm(b0, b1, 0x7632);
    float l0 = v0 - __uint_as_float(b0 & 0xffff0000u);
    float l1 = v1 - __uint_as_float(b1 & 0xffff0000u);
    asm("cvt.rn.bf16x2.f32 %0, %1, %2;" : "=r"(lw) : "f"(l1), "f"(l0));
}

#define LDSM_X4(r0, r1, r2, r3, addr) \
    asm volatile("ldmatrix.sync.aligned.m8n8.x4.shared.b16 {%0,%1,%2,%3}, [%4];" \
        : "=r"(r0), "=r"(r1), "=r"(r2), "=r"(r3) : "r"(addr))

#define MMA16816(c, a0, a1, a2, a3, b0, b1) \
    asm volatile("mma.sync.aligned.m16n8k16.row.col.f32.bf16.bf16.f32 " \
        "{%0,%1,%2,%3}, {%4,%5,%6,%7}, {%8,%9}, {%0,%1,%2,%3};" \
        : "+f"((c)[0]), "+f"((c)[1]), "+f"((c)[2]), "+f"((c)[3]) \
        : "r"(a0), "r"(a1), "r"(a2), "r"(a3), "r"(b0), "r"(b1))

// ---------------- 1) pack adjacency to bits ---------------------------------
__global__ void k_pack_adj(const int* __restrict__ adj) {
    int gw   = blockIdx.x * 8 + (threadIdx.x >> 5);
    int lane = threadIdx.x & 31;
    int m  = ((gw & 15) << 5) | lane;
    int bn = gw >> 4;
    int v  = adj[bn * NN + m] > 0;
    unsigned msk = __ballot_sync(0xffffffffu, v);
    if (lane == 0) g_adjb[gw] = msk;
}

// ---------------- 1b) split x and W^T into bf16 hi/lo -----------------------
__global__ void k_prep(const float* __restrict__ x, const float* __restrict__ W) {
    int tid = threadIdx.x;
    if (blockIdx.x < 2048) {
        int gid = blockIdx.x * 256 + tid;
        float4 v = ((const float4*)x)[gid];
        unsigned h0, l0, h1, l1;
        split2(v.x, v.y, h0, l0);
        split2(v.z, v.w, h1, l1);
        ((uint2*)g_x_hi)[gid] = make_uint2(h0, h1);
        ((uint2*)g_x_lo)[gid] = make_uint2(l0, l1);
    } else {
        int gid = (blockIdx.x - 2048) * 256 + tid;
        int idx = gid * 4;
        int h = idx >> 13, rem = idx & 8191;
        int f = rem >> 7, k0 = rem & 127;
        const float* wp = W + h * NF * FH + f;
        float v0 = wp[(k0 + 0) * FH], v1 = wp[(k0 + 1) * FH];
        float v2 = wp[(k0 + 2) * FH], v3 = wp[(k0 + 3) * FH];
        unsigned h0, l0, h1, l1;
        split2(v0, v1, h0, l0);
        split2(v2, v3, h1, l1);
        ((uint2*)g_WT_hi)[gid] = make_uint2(h0, h1);
        ((uint2*)g_WT_lo)[gid] = make_uint2(l0, l1);
    }
}

// ---------------- 2) h = x @ W per head via HMMA bf16x3 + epilogue ----------
#define HG_XH 0
#define HG_XL 16384
#define HG_WH 32768
#define HG_WL 49152
#define SMEM_HG 65536

__global__ __launch_bounds__(128) void k_head_gemm(const float* __restrict__ a1h,
                                                   const float* __restrict__ a2h) {
    extern __shared__ char sm[];
    uint32_t smb = smem_u32(sm);
    int head = blockIdx.z, b = blockIdx.y, n0 = blockIdx.x * 64;
    int hb = head * BB + b;
    int tid = threadIdx.x, warp = tid >> 5, lane = tid & 31;

    {
        const uint4* xh4 = (const uint4*)g_x_hi + (size_t)(b * NN + n0) * 16;
        const uint4* xl4 = (const uint4*)g_x_lo + (size_t)(b * NN + n0) * 16;
        const uint4* wh4 = (const uint4*)g_WT_hi + (size_t)head * FH * 16;
        const uint4* wl4 = (const uint4*)g_WT_lo + (size_t)head * FH * 16;
        #pragma unroll
        for (int i = 0; i < 8; i++) {
            int idx = tid + i * 128;
            int row = idx >> 4, kq = idx & 15;
            uint32_t off = (kq >> 3) * 8192 + SWZ(row * 128 + (kq & 7) * 16);
            *(uint4*)(sm + HG_XH + off) = xh4[idx];
            *(uint4*)(sm + HG_XL + off) = xl4[idx];
            *(uint4*)(sm + HG_WH + off) = wh4[idx];
            *(uint4*)(sm + HG_WL + off) = wl4[idx];
        }
    }
    __syncthreads();

    int q = lane >> 3, ri = lane & 7;
    int arow = warp * 16 + ((q & 1) << 3) + ri;
    int frow = ((q & 1) << 3) + ri;
    int akb  = (q >> 1) << 4;

    float c[8][4];
    #pragma unroll
    for (int i = 0; i < 8; i++)
        #pragma unroll
        for (int j = 0; j < 4; j++) c[i][j] = 0.f;

    #pragma unroll
    for (int kc = 0; kc < 8; kc++) {
        uint32_t ao = (kc >> 2) * 8192 + SWZ(arow * 128 + (kc & 3) * 32 + akb);
        uint32_t ah[4], al[4];
        LDSM_X4(ah[0], ah[1], ah[2], ah[3], smb + HG_XH + ao);
        LDSM_X4(al[0], al[1], al[2], al[3], smb + HG_XL + ao);
        #pragma unroll
        for (int np = 0; np < 4; np++) {
            uint32_t bo = (kc >> 2) * 8192 + SWZ((np * 16 + frow) * 128 + (kc & 3) * 32 + akb);
            uint32_t bh[4], bl[4];
            LDSM_X4(bh[0], bh[1], bh[2], bh[3], smb + HG_WH + bo);
            LDSM_X4(bl[0], bl[1], bl[2], bl[3], smb + HG_WL + bo);
            MMA16816(c[np*2],   ah[0], ah[1], ah[2], ah[3], bh[0], bh[2]);
            MMA16816(c[np*2],   ah[0], ah[1], ah[2], ah[3], bl[0], bl[2]);
            MMA16816(c[np*2],   al[0], al[1], al[2], al[3], bh[0], bh[2]);
            MMA16816(c[np*2+1], ah[0], ah[1], ah[2], ah[3], bh[1], bh[3]);
            MMA16816(c[np*2+1], ah[0], ah[1], ah[2], ah[3], bl[1], bl[3]);
            MMA16816(c[np*2+1], al[0], al[1], al[2], al[3], bh[1], bh[3]);
        }
    }

    __syncthreads();
    float* hstage = (float*)sm;
    int g4 = lane >> 2, t4 = lane & 3;
    int row0 = warp * 16 + g4;
    #pragma unroll
    for (int np = 0; np < 8; np++) {
        int col = np * 8 + t4 * 2;
        hstage[row0 * 65 + col]       = c[np][0];
        hstage[row0 * 65 + col + 1]   = c[np][1];
        hstage[(row0+8) * 65 + col]   = c[np][2];
        hstage[(row0+8) * 65 + col+1] = c[np][3];
    }
    __syncthreads();

    {
        int r = tid >> 1, half = tid & 1;
        float s1 = 0.f, s2 = 0.f;
        #pragma unroll
        for (int k2 = 0; k2 < 32; k2++) {
            int f = half * 32 + k2;
            float v = hstage[r * 65 + f];
            s1 = fmaf(v, a1h[head * FH + f], s1);
            s2 = fmaf(v, a2h[head * FH + f], s2);
        }
        s1 += __shfl_xor_sync(0xffffffffu, s1, 1);
        s2 += __shfl_xor_sync(0xffffffffu, s2, 1);
        if (half == 0) { g_f1[hb * NN + n0 + r] = s1; g_f2[hb * NN + n0 + r] = s2; }
    }
    {
        int f = tid >> 1, nh2 = tid & 1;
        unsigned hw[16], lw[16];
        #pragma unroll
        for (int k2 = 0; k2 < 16; k2++) {
            float v0 = hstage[(nh2 * 32 + 2 * k2)     * 65 + f];
            float v1 = hstage[(nh2 * 32 + 2 * k2 + 1) * 65 + f];
            split2(v0, v1, hw[k2], lw[k2]);
        }
        size_t base = ((size_t)(hb * FH + f)) * NN + n0 + nh2 * 32;
        #pragma unroll
        for (int i = 0; i < 4; i++) {
            *(uint4*)(g_hT_hi + base + i * 8) = make_uint4(hw[i*4], hw[i*4+1], hw[i*4+2], hw[i*4+3]);
            *(uint4*)(g_hT_lo + base + i * 8) = make_uint4(lw[i*4], lw[i*4+1], lw[i*4+2], lw[i*4+3]);
        }
    }
}

// ---------------- 3) tensor-core fused attention (mma.sync bf16x3) ----------
// Factorized exp + row sums via ones-MMA (no per-thread FADD chain, rinv
// straight from the accumulator). LDSM addresses hoisted out of chunk loop.
#define P_HI_OFF  0          // [128][64] bf16 SW128 rows = 16KB
#define P_LO_OFF  16384
#define BH_OFF    32768      // h^T chunk [64 f][64 m] bf16 = 8KB
#define BL_OFF    40960
#define F2P_OFF   49152      // 512 float2 = 4KB
#define SMEM_ATTN 53248
#define WOUT_OFF  34048      // 64x16 fp32 (epilogue; BH region dead)

__global__ __launch_bounds__(256, 2) void k_attn(const float* __restrict__ Wout) {
    extern __shared__ char sm[];
    uint32_t smb = smem_u32(sm);
    float2* f2p = (float2*)(sm + F2P_OFF);
    int head = blockIdx.z, b = blockIdx.y, n0 = blockIdx.x * 128;
    int hb = head * BB + b;
    int tid = threadIdx.x, warp = tid >> 5, lane = tid & 31;

    // factorized-exp tables
    #pragma unroll
    for (int i = 0; i < 2; i++) {
        int m = tid + i * 256;
        float f2v = g_f2[hb * NN + m];
        f2p[m] = make_float2(__expf(f2v), __expf(ALPHA * f2v));
    }
    int r = tid >> 1, half = tid & 1;
    float f1v = g_f1[hb * NN + n0 + r];
    float Ae = __expf(f1v), A2e = __expf(ALPHA * f1v), Ce = __expf(-f1v);
    const unsigned* gadj_row = g_adjb + (size_t)(b * NN + n0 + r) * 16;

    float c[8][4];
    #pragma unroll
    for (int i = 0; i < 8; i++)
        #pragma unroll
        for (int j = 0; j < 4; j++) c[i][j] = 0.f;
    float c2[4] = {0.f, 0.f, 0.f, 0.f};     // ones-MMA row sums

    int q = lane >> 3, ri = lane & 7;
    int arow = warp * 16 + ((q & 1) << 3) + ri;
    int frow = ((q & 1) << 3) + ri;
    int akb  = (q >> 1) << 4;

    // hoisted LDSM addresses (ch-invariant)
    uint32_t aoff[4], boff[4][4];
    #pragma unroll
    for (int kc = 0; kc < 4; kc++) {
        aoff[kc] = SWZ(arow * 128 + kc * 32 + akb);
        #pragma unroll
        for (int np = 0; np < 4; np++)
            boff[np][kc] = SWZ((np * 16 + frow) * 128 + kc * 32 + akb);
    }

    const uint4* shp = (const uint4*)g_hT_hi + (size_t)hb * FH * (NN / 8);
    const uint4* slp = (const uint4*)g_hT_lo + (size_t)hb * FH * (NN / 8);

    for (int ch = 0; ch < 8; ch++) {
        __syncthreads();
        // ---- produce P chunk [128 rows][64 m] hi/lo ----
        {
            unsigned word = gadj_row[ch * 2 + half];
            const float4* bp4 = (const float4*)(f2p + ch * 64 + half * 32);
            #pragma unroll
            for (int g = 0; g < 4; g++) {
                unsigned hh[4], ll[4];
                #pragma unroll
                for (int pj = 0; pj < 4; pj++) {
                    float4 B2 = bp4[g * 4 + pj];
                    int k0 = g * 8 + pj * 2;
                    bool p0 = B2.x > Ce;
                    bool p1 = B2.z > Ce;
                    float v0 = (p0 ? Ae : A2e) * (p0 ? B2.x : B2.y);
                    float v1 = (p1 ? Ae : A2e) * (p1 ? B2.z : B2.w);
                    v0 = ((word >> k0) & 1u) ? v0 : 0.f;
                    v1 = ((word >> (k0 + 1)) & 1u) ? v1 : 0.f;
                    split2t(v0, v1, hh[pj], ll[pj]);
                }
                uint32_t off = SWZ(r * 128 + half * 64 + g * 16);
                *(uint4*)(sm + P_HI_OFF + off) = make_uint4(hh[0], hh[1], hh[2], hh[3]);
                *(uint4*)(sm + P_LO_OFF + off) = make_uint4(ll[0], ll[1], ll[2], ll[3]);
            }
        }
        // ---- load h^T chunk [64 f][64 m] hi/lo ----
        #pragma unroll
        for (int i = 0; i < 2; i++) {
            int idx = tid + i * 256;
            int f = idx >> 3, jj = idx & 7;
            uint32_t off = SWZ(f * 128 + jj * 16);
            *(uint4*)(sm + BH_OFF + off) = shp[f * 64 + ch * 8 + jj];
            *(uint4*)(sm + BL_OFF + off) = slp[f * 64 + ch * 8 + jj];
        }
        __syncthreads();
        // ---- HMMA: 4 k-steps of 16, 8 n-tiles, 3 split terms + ones-MMA ----
        #pragma unroll
        for (int kc = 0; kc < 4; kc++) {
            uint32_t ah[4], al[4];
            LDSM_X4(ah[0], ah[1], ah[2], ah[3], smb + P_HI_OFF + aoff[kc]);
            LDSM_X4(al[0], al[1], al[2], al[3], smb + P_LO_OFF + aoff[kc]);
            MMA16816(c2, ah[0], ah[1], ah[2], ah[3], ONES2, ONES2);
            MMA16816(c2, al[0], al[1], al[2], al[3], ONES2, ONES2);
            #pragma unroll
            for (int np = 0; np < 4; np++) {
                uint32_t bh[4], bl[4];
                LDSM_X4(bh[0], bh[1], bh[2], bh[3], smb + BH_OFF + boff[np][kc]);
                LDSM_X4(bl[0], bl[1], bl[2], bl[3], smb + BL_OFF + boff[np][kc]);
                MMA16816(c[np*2],   ah[0], ah[1], ah[2], ah[3], bh[0], bh[2]);
                MMA16816(c[np*2],   ah[0], ah[1], ah[2], ah[3], bl[0], bl[2]);
                MMA16816(c[np*2],   al[0], al[1], al[2], al[3], bh[0], bh[2]);
                MMA16816(c[np*2+1], ah[0], ah[1], ah[2], ah[3], bh[1], bh[3]);
                MMA16816(c[np*2+1], ah[0], ah[1], ah[2], ah[3], bl[1], bl[3]);
                MMA16816(c[np*2+1], al[0], al[1], al[2], al[3], bh[1], bh[3]);
            }
        }
    }

    // rinv straight from ones-MMA accumulators (all lanes of a row identical)
    float rinv0 = 1.0f / c2[0];
    float rinv1 = 1.0f / c2[2];

    // ---- stage elu(h'/s) [128][65] fp32 + load Wout slice ----
    __syncthreads();
    float* hstage = (float*)sm;
    float* swout  = (float*)(sm + WOUT_OFF);
    ((float4*)swout)[tid] = ((const float4*)Wout)[head * 256 + tid];
    int g4 = lane >> 2, t4 = lane & 3;
    int row0 = warp * 16 + g4;
    #pragma unroll
    for (int np = 0; np < 8; np++) {
        int col = np * 8 + t4 * 2;
        float u0 = c[np][0] * rinv0, u1 = c[np][1] * rinv0;
        float v0 = c[np][2] * rinv1, v1 = c[np][3] * rinv1;
        u0 = u0 > 0.f ? u0 : expm1f(u0);
        u1 = u1 > 0.f ? u1 : expm1f(u1);
        v0 = v0 > 0.f ? v0 : expm1f(v0);
        v1 = v1 > 0.f ? v1 : expm1f(v1);
        hstage[row0 * 65 + col]         = u0;
        hstage[row0 * 65 + col + 1]     = u1;
        hstage[(row0 + 8) * 65 + col]   = v0;
        hstage[(row0 + 8) * 65 + col+1] = v1;
    }
    __syncthreads();

    // ---- partial hout ----
    {
        int row = tid >> 1, chf = tid & 1;
        float acc[8] = {};
        #pragma unroll 8
        for (int k = 0; k < 64; k++) {
            float a = hstage[row * 65 + k];
            const float* wr = swout + k * 16 + chf * 8;
            #pragma unroll
            for (int j = 0; j < 8; j++) acc[j] = fmaf(a, wr[j], acc[j]);
        }
        float* op = g_houtp + ((size_t)head * BB * NN + b * NN + n0 + row) * NC + chf * 8;
        *(float4*)op       = make_float4(acc[0], acc[1], acc[2], acc[3]);
        *(float4*)(op + 4) = make_float4(acc[4], acc[5], acc[6], acc[7]);
    }
}

// ---------------- 4) combine partial hout + f1o/f2o -------------------------
__global__ __launch_bounds__(256) void k_combine(const float* __restrict__ a1o,
                                                 const float* __restrict__ a2o) {
    int bn = blockIdx.x * 256 + threadIdx.x;
    float acc[16] = {};
    #pragma unroll
    for (int h = 0; h < NH; h++) {
        const float4* p = (const float4*)(g_houtp + ((size_t)h * BB * NN + bn) * NC);
        #pragma unroll
        for (int i = 0; i < 4; i++) {
            float4 v = p[i];
            acc[i*4]   += v.x; acc[i*4+1] += v.y;
            acc[i*4+2] += v.z; acc[i*4+3] += v.w;
        }
    }
    float4* op = (float4*)(g_hout + (size_t)bn * NC);
    #pragma unroll
    for (int i = 0; i < 4; i++)
        op[i] = make_float4(acc[i*4], acc[i*4+1], acc[i*4+2], acc[i*4+3]);
    float s1 = 0.f, s2 = 0.f;
    #pragma unroll
    for (int c = 0; c < 16; c++) { s1 = fmaf(acc[c], a1o[c], s1); s2 = fmaf(acc[c], a2o[c], s2); }
    g_f1o[bn] = s1; g_f2o[bn] = s2;
}

// ---------------- 5) output attention (F=16, factorized exp) ----------------
__global__ __launch_bounds__(256) void k_attn_out(float* __restrict__ out) {
    int b = blockIdx.y, n0 = blockIdx.x * 64;
    __shared__ float2   f2p[NN];        // 4KB
    __shared__ unsigned adjw[64 * 16];  // 4KB
    __shared__ float    hs[64 * 16];    // 4KB
    __shared__ float    ps[64 * 68];    // 17.4KB
    int tid = threadIdx.x;

    #pragma unroll
    for (int i = 0; i < 2; i++) {
        int m = tid + i * 256;
        float f2v = g_f2o[b * NN + m];
        f2p[m] = make_float2(__expf(f2v), __expf(ALPHA * f2v));
    }
    {
        const unsigned* ab = g_adjb + (size_t)(b * NN + n0) * 16;
        for (int i = tid; i < 1024; i += 256) adjw[i] = ab[i];
    }
    int r = tid >> 2, q = tid & 3;
    float f1v = g_f1o[b * NN + n0 + r];
    float Ae = __expf(f1v), A2e = __expf(ALPHA * f1v), Ce = __expf(-f1v);

    float s = 0.f;
    float4 acc = {0, 0, 0, 0};
    const float4* hg4 = (const float4*)g_hout + (size_t)b * NN * 4;
    for (int c = 0; c < 8; c++) {
        __syncthreads();
        ((float4*)hs)[tid] = hg4[c * 256 + tid];
        {
            unsigned word = adjw[(r << 4) + c * 2 + (q >> 1)];
            int sb = (q & 1) * 16;
            const float2* bp = f2p + c * 64 + q * 16;
            #pragma unroll
            for (int t = 0; t < 16; t++) {
                float2 Bv = bp[t];
                bool pos = Bv.x > Ce;
                float val = (pos ? Ae : A2e) * (pos ? Bv.x : Bv.y);
                val = ((word >> (sb + t)) & 1u) ? val : 0.f;
                ps[r * 68 + q * 16 + t] = val;
            }
        }
        __syncthreads();
        #pragma unroll 8
        for (int mm = 0; mm < 64; mm++) {
            float p = ps[r * 68 + mm];
            s += p;
            float4 hv = ((const float4*)hs)[mm * 4 + q];
            acc.x = fmaf(p, hv.x, acc.x); acc.y = fmaf(p, hv.y, acc.y);
            acc.z = fmaf(p, hv.z, acc.z); acc.w = fmaf(p, hv.w, acc.w);
        }
    }
    float rinv = 1.0f / s;
    acc.x *= rinv; acc.y *= rinv; acc.z *= rinv; acc.w *= rinv;
    *(float4*)&out[(size_t)(b * NN + n0 + r) * NC + (q << 2)] = acc;
}

// ---------------- launch ----------------------------------------------------
extern "C" void kernel_launch(void* const* d_in, const int* in_sizes, int n_in,
                              void* d_out, int out_size) {
    const float* x   = (const float*)d_in[0];
    const int*   adj = (const int*)  d_in[1];
    const float* Wh  = (const float*)d_in[2];
    const float* a1h = (const float*)d_in[3];
    const float* a2h = (const float*)d_in[4];
    const float* Wo  = (const float*)d_in[5];
    const float* a1o = (const float*)d_in[6];
    const float* a2o = (const float*)d_in[7];
    float* out = (float*)d_out;

    cudaFuncSetAttribute(k_head_gemm, cudaFuncAttributeMaxDynamicSharedMemorySize, SMEM_HG);
    cudaFuncSetAttribute(k_attn, cudaFuncAttributeMaxDynamicSharedMemorySize, SMEM_ATTN);

    k_pack_adj <<<BB * NN * 16 / 8, 256>>>(adj);
    k_prep     <<<2112, 256>>>(x, Wh);
    k_head_gemm<<<dim3(8, BB, NH), 128, SMEM_HG>>>(a1h, a2h);
    k_attn     <<<dim3(4, BB, NH), 256, SMEM_ATTN>>>(Wo);
    k_combine  <<<BB * NN / 256, 256>>>(a1o, a2o);
    k_attn_out <<<dim3(8, BB), 256>>>(out);
}

// round 12
// speedup vs baseline: 5.5392x; 1.0251x over previous
#include <cuda_runtime.h>
#include <cuda_bf16.h>
#include <math.h>
#include <stdint.h>

#define BB 32
#define NN 512
#define NF 128
#define FH 64
#define NH 8
#define NC 16
#define ALPHA 0.2f

// ---------------- scratch (device globals; allocation-free rule) -------------
__device__ float          g_f1[NH*BB*NN];
__device__ float          g_f2[NH*BB*NN];
__device__ unsigned       g_adjb[BB*NN*(NN/32)];    // adjacency bitmask [B][N][16]
__device__ __nv_bfloat16  g_x_hi[BB*NN*NF];         // x split hi [B*N][128]
__device__ __nv_bfloat16  g_x_lo[BB*NN*NF];
__device__ __nv_bfloat16  g_WT_hi[NH*FH*NF];        // W^T split [H][f][k]
__device__ __nv_bfloat16  g_WT_lo[NH*FH*NF];
__device__ __nv_bfloat16  g_hT_hi[NH*BB*FH*NN];     // h^T hi [H*B][f][m]
__device__ __nv_bfloat16  g_hT_lo[NH*BB*FH*NN];     // h^T lo
__device__ float          g_houtp[NH*BB*NN*NC];     // per-head partial hout
__device__ float          g_hout[BB*NN*NC];
__device__ float          g_f1o[BB*NN];
__device__ float          g_f2o[BB*NN];

// ---------------- helpers ----------------------------------------------------
__device__ __forceinline__ uint32_t smem_u32(const void* p) {
    uint32_t a;
    asm("{ .reg .u64 t; cvta.to.shared.u64 t, %1; cvt.u32.u64 %0, t; }"
        : "=r"(a) : "l"(p));
    return a;
}
#define SWZ(o) ((o) ^ ((((unsigned)(o)) >> 3) & 0x70))
#define ONES2 0x3F803F80u   // bf16x2 {1.0, 1.0}

__device__ __forceinline__ unsigned packbf2(__nv_bfloat16 a, __nv_bfloat16 b) {
    __nv_bfloat162 p; p.x = a; p.y = b;
    return *(unsigned*)&p;
}
__device__ __forceinline__ void split2(float v0, float v1, unsigned& hw, unsigned& lw) {
    __nv_bfloat16 h0 = __float2bfloat16(v0), h1 = __float2bfloat16(v1);
    __nv_bfloat16 l0 = __float2bfloat16(v0 - __bfloat162float(h0));
    __nv_bfloat16 l1 = __float2bfloat16(v1 - __bfloat162float(h1));
    hw = packbf2(h0, h1);
    lw = packbf2(l0, l1);
}
// truncation split: hi = top-16 bits (exact via PRMT), lo = v - hi (rn bf16x2)
__device__ __forceinline__ void split2t(float v0, float v1, unsigned& hw, unsigned& lw) {
    unsigned b0 = __float_as_uint(v0), b1 = __float_as_uint(v1);
    hw = __byte_perm(b0, b1, 0x7632);
    float l0 = v0 - __uint_as_float(b0 & 0xffff0000u);
    float l1 = v1 - __uint_as_float(b1 & 0xffff0000u);
    asm("cvt.rn.bf16x2.f32 %0, %1, %2;" : "=r"(lw) : "f"(l1), "f"(l0));
}

#define LDSM_X4(r0, r1, r2, r3, addr) \
    asm volatile("ldmatrix.sync.aligned.m8n8.x4.shared.b16 {%0,%1,%2,%3}, [%4];" \
        : "=r"(r0), "=r"(r1), "=r"(r2), "=r"(r3) : "r"(addr))

#define MMA16816(c, a0, a1, a2, a3, b0, b1) \
    asm volatile("mma.sync.aligned.m16n8k16.row.col.f32.bf16.bf16.f32 " \
        "{%0,%1,%2,%3}, {%4,%5,%6,%7}, {%8,%9}, {%0,%1,%2,%3};" \
        : "+f"((c)[0]), "+f"((c)[1]), "+f"((c)[2]), "+f"((c)[3]) \
        : "r"(a0), "r"(a1), "r"(a2), "r"(a3), "r"(b0), "r"(b1))

// ---------------- 1) pack adjacency to bits ---------------------------------
__global__ void k_pack_adj(const int* __restrict__ adj) {
    int gw   = blockIdx.x * 8 + (threadIdx.x >> 5);
    int lane = threadIdx.x & 31;
    int m  = ((gw & 15) << 5) | lane;
    int bn = gw >> 4;
    int v  = adj[bn * NN + m] > 0;
    unsigned msk = __ballot_sync(0xffffffffu, v);
    if (lane == 0) g_adjb[gw] = msk;
}

// ---------------- 1b) split x and W^T into bf16 hi/lo -----------------------
__global__ void k_prep(const float* __restrict__ x, const float* __restrict__ W) {
    int tid = threadIdx.x;
    if (blockIdx.x < 2048) {
        int gid = blockIdx.x * 256 + tid;
        float4 v = ((const float4*)x)[gid];
        unsigned h0, l0, h1, l1;
        split2(v.x, v.y, h0, l0);
        split2(v.z, v.w, h1, l1);
        ((uint2*)g_x_hi)[gid] = make_uint2(h0, h1);
        ((uint2*)g_x_lo)[gid] = make_uint2(l0, l1);
    } else {
        int gid = (blockIdx.x - 2048) * 256 + tid;
        int idx = gid * 4;
        int h = idx >> 13, rem = idx & 8191;
        int f = rem >> 7, k0 = rem & 127;
        const float* wp = W + h * NF * FH + f;
        float v0 = wp[(k0 + 0) * FH], v1 = wp[(k0 + 1) * FH];
        float v2 = wp[(k0 + 2) * FH], v3 = wp[(k0 + 3) * FH];
        unsigned h0, l0, h1, l1;
        split2(v0, v1, h0, l0);
        split2(v2, v3, h1, l1);
        ((uint2*)g_WT_hi)[gid] = make_uint2(h0, h1);
        ((uint2*)g_WT_lo)[gid] = make_uint2(l0, l1);
    }
}

// ---------------- 2) h = x @ W per head via HMMA bf16x3 + epilogue ----------
#define HG_XH 0
#define HG_XL 16384
#define HG_WH 32768
#define HG_WL 49152
#define SMEM_HG 65536

__global__ __launch_bounds__(128) void k_head_gemm(const float* __restrict__ a1h,
                                                   const float* __restrict__ a2h) {
    extern __shared__ char sm[];
    uint32_t smb = smem_u32(sm);
    int head = blockIdx.z, b = blockIdx.y, n0 = blockIdx.x * 64;
    int hb = head * BB + b;
    int tid = threadIdx.x, warp = tid >> 5, lane = tid & 31;

    {
        const uint4* xh4 = (const uint4*)g_x_hi + (size_t)(b * NN + n0) * 16;
        const uint4* xl4 = (const uint4*)g_x_lo + (size_t)(b * NN + n0) * 16;
        const uint4* wh4 = (const uint4*)g_WT_hi + (size_t)head * FH * 16;
        const uint4* wl4 = (const uint4*)g_WT_lo + (size_t)head * FH * 16;
        #pragma unroll
        for (int i = 0; i < 8; i++) {
            int idx = tid + i * 128;
            int row = idx >> 4, kq = idx & 15;
            uint32_t off = (kq >> 3) * 8192 + SWZ(row * 128 + (kq & 7) * 16);
            *(uint4*)(sm + HG_XH + off) = xh4[idx];
            *(uint4*)(sm + HG_XL + off) = xl4[idx];
            *(uint4*)(sm + HG_WH + off) = wh4[idx];
            *(uint4*)(sm + HG_WL + off) = wl4[idx];
        }
    }
    __syncthreads();

    int q = lane >> 3, ri = lane & 7;
    int arow = warp * 16 + ((q & 1) << 3) + ri;
    int frow = ((q & 1) << 3) + ri;
    int akb  = (q >> 1) << 4;

    float c[8][4];
    #pragma unroll
    for (int i = 0; i < 8; i++)
        #pragma unroll
        for (int j = 0; j < 4; j++) c[i][j] = 0.f;

    #pragma unroll
    for (int kc = 0; kc < 8; kc++) {
        uint32_t ao = (kc >> 2) * 8192 + SWZ(arow * 128 + (kc & 3) * 32 + akb);
        uint32_t ah[4], al[4];
        LDSM_X4(ah[0], ah[1], ah[2], ah[3], smb + HG_XH + ao);
        LDSM_X4(al[0], al[1], al[2], al[3], smb + HG_XL + ao);
        #pragma unroll
        for (int np = 0; np < 4; np++) {
            uint32_t bo = (kc >> 2) * 8192 + SWZ((np * 16 + frow) * 128 + (kc & 3) * 32 + akb);
            uint32_t bh[4], bl[4];
            LDSM_X4(bh[0], bh[1], bh[2], bh[3], smb + HG_WH + bo);
            LDSM_X4(bl[0], bl[1], bl[2], bl[3], smb + HG_WL + bo);
            MMA16816(c[np*2],   ah[0], ah[1], ah[2], ah[3], bh[0], bh[2]);
            MMA16816(c[np*2],   ah[0], ah[1], ah[2], ah[3], bl[0], bl[2]);
            MMA16816(c[np*2],   al[0], al[1], al[2], al[3], bh[0], bh[2]);
            MMA16816(c[np*2+1], ah[0], ah[1], ah[2], ah[3], bh[1], bh[3]);
            MMA16816(c[np*2+1], ah[0], ah[1], ah[2], ah[3], bl[1], bl[3]);
            MMA16816(c[np*2+1], al[0], al[1], al[2], al[3], bh[1], bh[3]);
        }
    }

    __syncthreads();
    float* hstage = (float*)sm;
    int g4 = lane >> 2, t4 = lane & 3;
    int row0 = warp * 16 + g4;
    #pragma unroll
    for (int np = 0; np < 8; np++) {
        int col = np * 8 + t4 * 2;
        hstage[row0 * 65 + col]       = c[np][0];
        hstage[row0 * 65 + col + 1]   = c[np][1];
        hstage[(row0+8) * 65 + col]   = c[np][2];
        hstage[(row0+8) * 65 + col+1] = c[np][3];
    }
    __syncthreads();

    {
        int r = tid >> 1, half = tid & 1;
        float s1 = 0.f, s2 = 0.f;
        #pragma unroll
        for (int k2 = 0; k2 < 32; k2++) {
            int f = half * 32 + k2;
            float v = hstage[r * 65 + f];
            s1 = fmaf(v, a1h[head * FH + f], s1);
            s2 = fmaf(v, a2h[head * FH + f], s2);
        }
        s1 += __shfl_xor_sync(0xffffffffu, s1, 1);
        s2 += __shfl_xor_sync(0xffffffffu, s2, 1);
        if (half == 0) { g_f1[hb * NN + n0 + r] = s1; g_f2[hb * NN + n0 + r] = s2; }
    }
    {
        int f = tid >> 1, nh2 = tid & 1;
        unsigned hw[16], lw[16];
        #pragma unroll
        for (int k2 = 0; k2 < 16; k2++) {
            float v0 = hstage[(nh2 * 32 + 2 * k2)     * 65 + f];
            float v1 = hstage[(nh2 * 32 + 2 * k2 + 1) * 65 + f];
            split2(v0, v1, hw[k2], lw[k2]);
        }
        size_t base = ((size_t)(hb * FH + f)) * NN + n0 + nh2 * 32;
        #pragma unroll
        for (int i = 0; i < 4; i++) {
            *(uint4*)(g_hT_hi + base + i * 8) = make_uint4(hw[i*4], hw[i*4+1], hw[i*4+2], hw[i*4+3]);
            *(uint4*)(g_hT_lo + base + i * 8) = make_uint4(lw[i*4], lw[i*4+1], lw[i*4+2], lw[i*4+3]);
        }
    }
}

// ---------------- 3) tensor-core fused attention (mma.sync bf16x3) ----------
// Double-buffered chunk pipeline: MMA(buf j) overlaps production(buf j^1),
// one sync per chunk. exp(leaky(z)) = max(e^z, e^{.2z}) (exp monotone).
#define BUF_SZ    49152      // P_HI 16K + P_LO 16K + BH 8K + BL 8K
#define P_HI_R    0
#define P_LO_R    16384
#define BH_R      32768
#define BL_R      40960
#define F2P_OFF   98304      // 512 float2 = 4KB
#define SMEM_ATTN 102400
#define WOUT_OFF  34048      // epilogue Wout slice (buffer region dead)

__global__ __launch_bounds__(256, 2) void k_attn(const float* __restrict__ Wout) {
    extern __shared__ char sm[];
    uint32_t smb = smem_u32(sm);
    float2* f2p = (float2*)(sm + F2P_OFF);
    int head = blockIdx.z, b = blockIdx.y, n0 = blockIdx.x * 128;
    int hb = head * BB + b;
    int tid = threadIdx.x, warp = tid >> 5, lane = tid & 31;

    // factorized-exp tables
    #pragma unroll
    for (int i = 0; i < 2; i++) {
        int m = tid + i * 256;
        float f2v = g_f2[hb * NN + m];
        f2p[m] = make_float2(__expf(f2v), __expf(ALPHA * f2v));
    }
    int r = tid >> 1, half = tid & 1;
    float f1v = g_f1[hb * NN + n0 + r];
    float Ae = __expf(f1v), A2e = __expf(ALPHA * f1v);
    const unsigned* gadj_row = g_adjb + (size_t)(b * NN + n0 + r) * 16;

    float c[8][4];
    #pragma unroll
    for (int i = 0; i < 8; i++)
        #pragma unroll
        for (int j = 0; j < 4; j++) c[i][j] = 0.f;
    float c2[4] = {0.f, 0.f, 0.f, 0.f};     // ones-MMA row sums

    int q = lane >> 3, ri = lane & 7;
    int arow = warp * 16 + ((q & 1) << 3) + ri;
    int frow = ((q & 1) << 3) + ri;
    int akb  = (q >> 1) << 4;

    // hoisted LDSM addresses (buffer-relative)
    uint32_t aoff[4], boff[4][4];
    #pragma unroll
    for (int kc = 0; kc < 4; kc++) {
        aoff[kc] = SWZ(arow * 128 + kc * 32 + akb);
        #pragma unroll
        for (int np = 0; np < 4; np++)
            boff[np][kc] = SWZ((np * 16 + frow) * 128 + kc * 32 + akb);
    }

    const uint4* shp = (const uint4*)g_hT_hi + (size_t)hb * FH * (NN / 8);
    const uint4* slp = (const uint4*)g_hT_lo + (size_t)hb * FH * (NN / 8);

    // hoisted B-load geometry
    int bf = tid >> 3, bj = tid & 7;
    uint32_t bso  = SWZ(bf * 128 + bj * 16);
    uint32_t bso1 = SWZ((bf + 32) * 128 + bj * 16);
    int bgi0 = bf * 64 + bj, bgi1 = (bf + 32) * 64 + bj;

    #define PRODUCE(chv, bufbase) { \
        unsigned word = gadj_row[(chv) * 2 + half]; \
        const float4* bp4 = (const float4*)(f2p + (chv) * 64 + half * 32); \
        char* Ph = sm + (bufbase) + P_HI_R; \
        char* Pl = sm + (bufbase) + P_LO_R; \
        _Pragma("unroll") \
        for (int g = 0; g < 4; g++) { \
            unsigned hh[4], ll[4]; \
            _Pragma("unroll") \
            for (int pj = 0; pj < 4; pj++) { \
                float4 B2 = bp4[g * 4 + pj]; \
                int k0 = g * 8 + pj * 2; \
                float v0 = fmaxf(Ae * B2.x, A2e * B2.y); \
                float v1 = fmaxf(Ae * B2.z, A2e * B2.w); \
                v0 = ((word >> k0) & 1u) ? v0 : 0.f; \
                v1 = ((word >> (k0 + 1)) & 1u) ? v1 : 0.f; \
                split2t(v0, v1, hh[pj], ll[pj]); \
            } \
            uint32_t off = SWZ(r * 128 + half * 64 + g * 16); \
            *(uint4*)(Ph + off) = make_uint4(hh[0], hh[1], hh[2], hh[3]); \
            *(uint4*)(Pl + off) = make_uint4(ll[0], ll[1], ll[2], ll[3]); \
        } \
        *(uint4*)(sm + (bufbase) + BH_R + bso)  = shp[bgi0 + (chv) * 8]; \
        *(uint4*)(sm + (bufbase) + BH_R + bso1) = shp[bgi1 + (chv) * 8]; \
        *(uint4*)(sm + (bufbase) + BL_R + bso)  = slp[bgi0 + (chv) * 8]; \
        *(uint4*)(sm + (bufbase) + BL_R + bso1) = slp[bgi1 + (chv) * 8]; \
    }

    // f2p table must be visible to ALL threads before any production reads it
    __syncthreads();
    PRODUCE(0, 0)
    __syncthreads();

    for (int ch = 0; ch < 8; ch++) {
        uint32_t bufb = (ch & 1) * BUF_SZ;
        // ---- HMMA from buffer j ----
        #pragma unroll
        for (int kc = 0; kc < 4; kc++) {
            uint32_t ah[4], al[4];
            LDSM_X4(ah[0], ah[1], ah[2], ah[3], smb + bufb + P_HI_R + aoff[kc]);
            LDSM_X4(al[0], al[1], al[2], al[3], smb + bufb + P_LO_R + aoff[kc]);
            MMA16816(c2, ah[0], ah[1], ah[2], ah[3], ONES2, ONES2);
            MMA16816(c2, al[0], al[1], al[2], al[3], ONES2, ONES2);
            #pragma unroll
            for (int np = 0; np < 4; np++) {
                uint32_t bh[4], bl[4];
                LDSM_X4(bh[0], bh[1], bh[2], bh[3], smb + bufb + BH_R + boff[np][kc]);
                LDSM_X4(bl[0], bl[1], bl[2], bl[3], smb + bufb + BL_R + boff[np][kc]);
                MMA16816(c[np*2],   ah[0], ah[1], ah[2], ah[3], bh[0], bh[2]);
                MMA16816(c[np*2],   ah[0], ah[1], ah[2], ah[3], bl[0], bl[2]);
                MMA16816(c[np*2],   al[0], al[1], al[2], al[3], bh[0], bh[2]);
                MMA16816(c[np*2+1], ah[0], ah[1], ah[2], ah[3], bh[1], bh[3]);
                MMA16816(c[np*2+1], ah[0], ah[1], ah[2], ah[3], bl[1], bl[3]);
                MMA16816(c[np*2+1], al[0], al[1], al[2], al[3], bh[1], bh[3]);
            }
        }
        // ---- produce next chunk into the other buffer ----
        if (ch < 7) PRODUCE(ch + 1, (uint32_t)(((ch + 1) & 1) * BUF_SZ))
        __syncthreads();
    }

    // rinv straight from ones-MMA accumulators
    float rinv0 = 1.0f / c2[0];
    float rinv1 = 1.0f / c2[2];

    // ---- stage elu(h'/s) [128][65] fp32 + load Wout slice ----
    float* hstage = (float*)sm;
    float* swout  = (float*)(sm + WOUT_OFF);
    ((float4*)swout)[tid] = ((const float4*)Wout)[head * 256 + tid];
    int g4 = lane >> 2, t4 = lane & 3;
    int row0 = warp * 16 + g4;
    #pragma unroll
    for (int np = 0; np < 8; np++) {
        int col = np * 8 + t4 * 2;
        float u0 = c[np][0] * rinv0, u1 = c[np][1] * rinv0;
        float v0 = c[np][2] * rinv1, v1 = c[np][3] * rinv1;
        u0 = u0 > 0.f ? u0 : expm1f(u0);
        u1 = u1 > 0.f ? u1 : expm1f(u1);
        v0 = v0 > 0.f ? v0 : expm1f(v0);
        v1 = v1 > 0.f ? v1 : expm1f(v1);
        hstage[row0 * 65 + col]         = u0;
        hstage[row0 * 65 + col + 1]     = u1;
        hstage[(row0 + 8) * 65 + col]   = v0;
        hstage[(row0 + 8) * 65 + col+1] = v1;
    }
    __syncthreads();

    // ---- partial hout ----
    {
        int row = tid >> 1, chf = tid & 1;
        float acc[8] = {};
        #pragma unroll 8
        for (int k = 0; k < 64; k++) {
            float a = hstage[row * 65 + k];
            const float* wr = swout + k * 16 + chf * 8;
            #pragma unroll
            for (int j = 0; j < 8; j++) acc[j] = fmaf(a, wr[j], acc[j]);
        }
        float* op = g_houtp + ((size_t)head * BB * NN + b * NN + n0 + row) * NC + chf * 8;
        *(float4*)op       = make_float4(acc[0], acc[1], acc[2], acc[3]);
        *(float4*)(op + 4) = make_float4(acc[4], acc[5], acc[6], acc[7]);
    }
}

// ---------------- 4) combine partial hout + f1o/f2o -------------------------
__global__ __launch_bounds__(256) void k_combine(const float* __restrict__ a1o,
                                                 const float* __restrict__ a2o) {
    int bn = blockIdx.x * 256 + threadIdx.x;
    float acc[16] = {};
    #pragma unroll
    for (int h = 0; h < NH; h++) {
        const float4* p = (const float4*)(g_houtp + ((size_t)h * BB * NN + bn) * NC);
        #pragma unroll
        for (int i = 0; i < 4; i++) {
            float4 v = p[i];
            acc[i*4]   += v.x; acc[i*4+1] += v.y;
            acc[i*4+2] += v.z; acc[i*4+3] += v.w;
        }
    }
    float4* op = (float4*)(g_hout + (size_t)bn * NC);
    #pragma unroll
    for (int i = 0; i < 4; i++)
        op[i] = make_float4(acc[i*4], acc[i*4+1], acc[i*4+2], acc[i*4+3]);
    float s1 = 0.f, s2 = 0.f;
    #pragma unroll
    for (int c = 0; c < 16; c++) { s1 = fmaf(acc[c], a1o[c], s1); s2 = fmaf(acc[c], a2o[c], s2); }
    g_f1o[bn] = s1; g_f2o[bn] = s2;
}

// ---------------- 5) output attention (F=16, max-factorized exp) ------------
__global__ __launch_bounds__(256) void k_attn_out(float* __restrict__ out) {
    int b = blockIdx.y, n0 = blockIdx.x * 64;
    __shared__ float2   f2p[NN];        // 4KB
    __shared__ unsigned adjw[64 * 16];  // 4KB
    __shared__ float    hs[64 * 16];    // 4KB
    __shared__ float    ps[64 * 68];    // 17.4KB
    int tid = threadIdx.x;

    #pragma unroll
    for (int i = 0; i < 2; i++) {
        int m = tid + i * 256;
        float f2v = g_f2o[b * NN + m];
        f2p[m] = make_float2(__expf(f2v), __expf(ALPHA * f2v));
    }
    {
        const unsigned* ab = g_adjb + (size_t)(b * NN + n0) * 16;
        for (int i = tid; i < 1024; i += 256) adjw[i] = ab[i];
    }
    int r = tid >> 2, q = tid & 3;
    float f1v = g_f1o[b * NN + n0 + r];
    float Ae = __expf(f1v), A2e = __expf(ALPHA * f1v);

    float s = 0.f;
    float4 acc = {0, 0, 0, 0};
    const float4* hg4 = (const float4*)g_hout + (size_t)b * NN * 4;
    for (int c = 0; c < 8; c++) {
        __syncthreads();
        ((float4*)hs)[tid] = hg4[c * 256 + tid];
        {
            unsigned word = adjw[(r << 4) + c * 2 + (q >> 1)];
            int sb = (q & 1) * 16;
            const float2* bp = f2p + c * 64 + q * 16;
            #pragma unroll
            for (int t = 0; t < 16; t++) {
                float2 Bv = bp[t];
                float val = fmaxf(Ae * Bv.x, A2e * Bv.y);
                val = ((word >> (sb + t)) & 1u) ? val : 0.f;
                ps[r * 68 + q * 16 + t] = val;
            }
        }
        __syncthreads();
        #pragma unroll 8
        for (int mm = 0; mm < 64; mm++) {
            float p = ps[r * 68 + mm];
            s += p;
            float4 hv = ((const float4*)hs)[mm * 4 + q];
            acc.x = fmaf(p, hv.x, acc.x); acc.y = fmaf(p, hv.y, acc.y);
            acc.z = fmaf(p, hv.z, acc.z); acc.w = fmaf(p, hv.w, acc.w);
        }
    }
    float rinv = 1.0f / s;
    acc.x *= rinv; acc.y *= rinv; acc.z *= rinv; acc.w *= rinv;
    *(float4*)&out[(size_t)(b * NN + n0 + r) * NC + (q << 2)] = acc;
}

// ---------------- launch ----------------------------------------------------
extern "C" void kernel_launch(void* const* d_in, const int* in_sizes, int n_in,
                              void* d_out, int out_size) {
    const float* x   = (const float*)d_in[0];
    const int*   adj = (const int*)  d_in[1];
    const float* Wh  = (const float*)d_in[2];
    const float* a1h = (const float*)d_in[3];
    const float* a2h = (const float*)d_in[4];
    const float* Wo  = (const float*)d_in[5];
    const float* a1o = (const float*)d_in[6];
    const float* a2o = (const float*)d_in[7];
    float* out = (float*)d_out;

    cudaFuncSetAttribute(k_head_gemm, cudaFuncAttributeMaxDynamicSharedMemorySize, SMEM_HG);
    cudaFuncSetAttribute(k_attn, cudaFuncAttributeMaxDynamicSharedMemorySize, SMEM_ATTN);

    k_pack_adj <<<BB * NN * 16 / 8, 256>>>(adj);
    k_prep     <<<2112, 256>>>(x, Wh);
    k_head_gemm<<<dim3(8, BB, NH), 128, SMEM_HG>>>(a1h, a2h);
    k_attn     <<<dim3(4, BB, NH), 256, SMEM_ATTN>>>(Wo);
    k_combine  <<<BB * NN / 256, 256>>>(a1o, a2o);
    k_attn_out <<<dim3(8, BB), 256>>>(out);
}